// round 1
// baseline (speedup 1.0000x reference)
#include <cuda_runtime.h>
#include <math.h>

#define NMAX 20000
#define EMAX 320000

// ---------------- scratch (device globals; no runtime allocation) ----------
__device__ float g_packed[NMAX * 32 * 16];   // per (n,c): [g0, g1[3], g2[9], pad3]
__device__ float g_acc[NMAX * 32 * 16];      // accumulated messages, same layout
__device__ float g_F0[NMAX * 128];           // features for y0 GEMM
__device__ float g_F1[NMAX * 3 * 96];        // features for y1 GEMM
__device__ float g_F2[NMAX * 9 * 128];       // features for y2 GEMM
__device__ float g_Y0[NMAX * 32];
__device__ float g_G [NMAX * 96];            // gate pre-activations
__device__ float g_Y1[NMAX * 3 * 32];
__device__ float g_Y2[NMAX * 9 * 32];
__device__ float g_B0[128 * 32];             // stacked [U0;V0;V3;V6]
__device__ float g_B1[96 * 32];              // stacked [U1;V1;V5]
__device__ float g_B2[128 * 32];             // stacked [U2;V2;V4;V7]
__device__ float g_Bg[32 * 96];              // [Wg0|Wg1|Wg2]

// ---------------- helpers ---------------------------------------------------
__device__ __forceinline__ void red_add_v4(float* addr, float x, float y, float z, float w) {
    asm volatile(
        "{\n\t"
        ".reg .u64 a;\n\t"
        "cvta.to.global.u64 a, %0;\n\t"
        "red.global.add.v4.f32 [a], {%1, %2, %3, %4};\n\t"
        "}"
        :: "l"(addr), "f"(x), "f"(y), "f"(z), "f"(w) : "memory");
}

// ---------------- kernel 0: pack stacked weight matrices -------------------
__global__ void pack_weights(const float* __restrict__ U, const float* __restrict__ V,
                             const float* __restrict__ Wg) {
    int t = blockIdx.x * blockDim.x + threadIdx.x;
    if (t >= 1024) return;
    int c = t >> 5, d = t & 31;
    int cd = c * 32 + d;
    // B0 = [U0; V0; V3; V6]   rows f*32+c, cols d  => linear f*1024 + t
    g_B0[t]        = U[cd];
    g_B0[1024 + t] = V[cd];
    g_B0[2048 + t] = V[3072 + cd];
    g_B0[3072 + t] = V[6144 + cd];
    // B1 = [U1; V1; V5]
    g_B1[t]        = U[1024 + cd];
    g_B1[1024 + t] = V[1024 + cd];
    g_B1[2048 + t] = V[5120 + cd];
    // B2 = [U2; V2; V4; V7]
    g_B2[t]        = U[2048 + cd];
    g_B2[1024 + t] = V[2048 + cd];
    g_B2[2048 + t] = V[4096 + cd];
    g_B2[3072 + t] = V[7168 + cd];
    // Bg: [32 x 96] = [Wg0 | Wg1 | Wg2]
    g_Bg[c * 96 + d]      = Wg[cd];
    g_Bg[c * 96 + 32 + d] = Wg[1024 + cd];
    g_Bg[c * 96 + 64 + d] = Wg[2048 + cd];
}

// ---------------- kernel 1: repack node features + zero accumulator --------
__global__ void prep_kernel(const float* __restrict__ node0, const float* __restrict__ node1,
                            const float* __restrict__ node2, int N) {
    int t = blockIdx.x * blockDim.x + threadIdx.x;
    if (t >= N * 32) return;
    const float* p1 = &node1[(long)t * 3];
    const float* p2 = &node2[(long)t * 9];
    float4 o0 = make_float4(node0[t], p1[0], p1[1], p1[2]);
    float4 o1 = make_float4(p2[0], p2[1], p2[2], p2[3]);
    float4 o2 = make_float4(p2[4], p2[5], p2[6], p2[7]);
    float4 o3 = make_float4(p2[8], 0.f, 0.f, 0.f);
    float4* dp = (float4*)&g_packed[(long)t * 16];
    dp[0] = o0; dp[1] = o1; dp[2] = o2; dp[3] = o3;
    float4 z = make_float4(0.f, 0.f, 0.f, 0.f);
    float4* da = (float4*)&g_acc[(long)t * 16];
    da[0] = z; da[1] = z; da[2] = z; da[3] = z;
}

// ---------------- kernel 2: edge messages + scatter -------------------------
// One warp per edge, lane = channel. m2 = r x r collapses contractions:
//   s1 = g1 . r,  v2 = g2 . r,  s2 = r . g2 . r
__global__ void edge_kernel(const float* __restrict__ rij, const float* __restrict__ Wrad,
                            const int* __restrict__ idx_i, const int* __restrict__ idx_j,
                            int E) {
    __shared__ float sW[11 * 8 * 32];
    for (int t = threadIdx.x; t < 2816; t += blockDim.x) sW[t] = Wrad[t];
    __syncthreads();
    int lane = threadIdx.x & 31;
    int warp = threadIdx.x >> 5;
    for (int e = blockIdx.x * 8 + warp; e < E; e += gridDim.x * 8) {
        float rx = __ldg(&rij[e * 3 + 0]);
        float ry = __ldg(&rij[e * 3 + 1]);
        float rz = __ldg(&rij[e * 3 + 2]);
        int ii = __ldg(&idx_i[e]);
        int jj = __ldg(&idx_j[e]);
        float d2 = rx * rx + ry * ry + rz * rz + 1e-12f;
        float dist = sqrtf(d2);
        float inv = 1.0f / dist;
        rx *= inv; ry *= inv; rz *= inv;
        float xx = fminf(dist * 0.2f, 1.0f);
        float fc = 0.5f * (__cosf(3.14159265358979f * xx) + 1.0f);
        float w[11];
        #pragma unroll
        for (int p = 0; p < 11; p++) w[p] = 0.f;
        #pragma unroll
        for (int b = 0; b < 8; b++) {
            float cb = 0.5f + (4.5f / 7.f) * (float)b;
            float tt = dist - cb;
            float rb = __expf(-4.f * tt * tt) * fc;
            #pragma unroll
            for (int p = 0; p < 11; p++) w[p] += rb * sW[(p * 8 + b) * 32 + lane];
        }
        // gather node_j features (custom packed layout, 64B/lane)
        const float4* src = (const float4*)&g_packed[((long)jj * 32 + lane) * 16];
        float4 q0 = src[0], q1 = src[1], q2 = src[2], q3 = src[3];
        float g0 = q0.x, g1x = q0.y, g1y = q0.z, g1z = q0.w;
        float s1 = g1x * rx + g1y * ry + g1z * rz;
        float v2x = q1.x * rx + q1.y * ry + q1.z * rz;
        float v2y = q1.w * rx + q2.x * ry + q2.y * rz;
        float v2z = q2.z * rx + q2.w * ry + q3.x * rz;
        float s2 = v2x * rx + v2y * ry + v2z * rz;
        // msg0
        float msg0 = g0 * w[0] + s1 * w[4] + s2 * w[9];
        // msg1[a] = (g0 w1 + s1 w6) r_a + w3 g1_a + w8 v2_a
        float cc = g0 * w[1] + s1 * w[6];
        float m1x = cc * rx + g1x * w[3] + w[8] * v2x;
        float m1y = cc * ry + g1y * w[3] + w[8] * v2y;
        float m1z = cc * rz + g1z * w[3] + w[8] * v2z;
        // msg2[ab] = w7 g2_ab + (g0 w2 r_a + w5 g1_a + w10 v2_a) r_b
        float g0w2 = g0 * w[2];
        float pax = g0w2 * rx + w[5] * g1x + w[10] * v2x;
        float pay = g0w2 * ry + w[5] * g1y + w[10] * v2y;
        float paz = g0w2 * rz + w[5] * g1z + w[10] * v2z;
        float* dst = &g_acc[((long)ii * 32 + lane) * 16];
        red_add_v4(dst + 0, msg0, m1x, m1y, m1z);
        red_add_v4(dst + 4,
                   w[7] * q1.x + pax * rx, w[7] * q1.y + pax * ry,
                   w[7] * q1.z + pax * rz, w[7] * q1.w + pay * rx);
        red_add_v4(dst + 8,
                   w[7] * q2.x + pay * ry, w[7] * q2.y + pay * rz,
                   w[7] * q2.z + paz * rx, w[7] * q2.w + paz * ry);
        red_add_v4(dst + 12, w[7] * q3.x + paz * rz, 0.f, 0.f, 0.f);
    }
}

// ---------------- kernel 3: build GEMM feature matrices --------------------
__global__ void feat_kernel(int N) {
    int t = blockIdx.x * blockDim.x + threadIdx.x;
    if (t >= N * 32) return;
    int n = t >> 5, c = t & 31;
    const float4* src = (const float4*)&g_acc[(long)t * 16];
    float4 q0 = src[0], q1 = src[1], q2 = src[2], q3 = src[3];
    const float s = 1.f / 16.f;   // NORM_FACTOR
    float a0 = q0.x * s;
    float a1[3] = {q0.y * s, q0.z * s, q0.w * s};
    float a2[9] = {q1.x * s, q1.y * s, q1.z * s, q1.w * s,
                   q2.x * s, q2.y * s, q2.z * s, q2.w * s, q3.x * s};
    // F0: [a0 | a0^2 | |a1|^2 | |a2|^2]
    float* f0 = &g_F0[(long)n * 128];
    f0[c]      = a0;
    f0[32 + c] = a0 * a0;
    f0[64 + c] = a1[0] * a1[0] + a1[1] * a1[1] + a1[2] * a1[2];
    float s22 = 0.f;
    #pragma unroll
    for (int i = 0; i < 9; i++) s22 += a2[i] * a2[i];
    f0[96 + c] = s22;
    // F1 rows (n, b): [a1_b | a0 a1_b | sum_k a1_k a2_kb]
    #pragma unroll
    for (int a = 0; a < 3; a++) {
        float* f1 = &g_F1[((long)n * 3 + a) * 96];
        f1[c]      = a1[a];
        f1[32 + c] = a0 * a1[a];
        f1[64 + c] = a1[0] * a2[a] + a1[1] * a2[3 + a] + a1[2] * a2[6 + a];
    }
    // F2 rows (n, a*3+b): [a2_ab | a0 a2_ab | a1_a a1_b | sum_k a2_ak a2_kb]
    #pragma unroll
    for (int a = 0; a < 3; a++) {
        #pragma unroll
        for (int b = 0; b < 3; b++) {
            int sidx = a * 3 + b;
            float* f2 = &g_F2[((long)n * 9 + sidx) * 128];
            f2[c]      = a2[sidx];
            f2[32 + c] = a0 * a2[sidx];
            f2[64 + c] = a1[a] * a1[b];
            f2[96 + c] = a2[a * 3 + 0] * a2[b] + a2[a * 3 + 1] * a2[3 + b]
                       + a2[a * 3 + 2] * a2[6 + b];
        }
    }
}

// ---------------- kernel 4: tiled fp32 GEMM  C[M,NC] = A[M,K] @ B[K,NC] ----
// block: 128 rows x 32 cols, 256 threads, 4x4 micro-tile, K chunked by 32.
__global__ void gemm_kernel(const float* __restrict__ A, const float* __restrict__ B,
                            float* __restrict__ Cmat, int M, int K, int NC) {
    __shared__ float sA[128 * 33];
    __shared__ float sB[32 * 32];
    int tid = threadIdx.x;
    int m0 = blockIdx.x * 128;
    int cblk = blockIdx.y * 32;
    int dg = tid & 7, rg = tid >> 3;
    int c0 = dg * 4, r0 = rg * 4;
    float acc[4][4] = {};
    for (int kc = 0; kc < K; kc += 32) {
        for (int idx = tid; idx < 128 * 32; idx += 256) {
            int r = idx >> 5, kk = idx & 31;
            int m = m0 + r;
            sA[r * 33 + kk] = (m < M) ? A[(long)m * K + kc + kk] : 0.f;
        }
        for (int idx = tid; idx < 32 * 32; idx += 256) {
            int kk = idx >> 5, d = idx & 31;
            sB[kk * 32 + d] = B[(long)(kc + kk) * NC + cblk + d];
        }
        __syncthreads();
        #pragma unroll
        for (int kk = 0; kk < 32; kk++) {
            float4 b4 = *(const float4*)&sB[kk * 32 + c0];
            #pragma unroll
            for (int i = 0; i < 4; i++) {
                float a = sA[(r0 + i) * 33 + kk];
                acc[i][0] += a * b4.x;
                acc[i][1] += a * b4.y;
                acc[i][2] += a * b4.z;
                acc[i][3] += a * b4.w;
            }
        }
        __syncthreads();
    }
    #pragma unroll
    for (int i = 0; i < 4; i++) {
        int m = m0 + r0 + i;
        if (m < M) {
            float4 v = make_float4(acc[i][0], acc[i][1], acc[i][2], acc[i][3]);
            *(float4*)&Cmat[(long)m * NC + cblk + c0] = v;
        }
    }
}

// ---------------- kernel 5: gated nonlinearity + residual ------------------
__global__ void final_kernel(const float* __restrict__ node0, const float* __restrict__ node1,
                             const float* __restrict__ node2, float* __restrict__ out, int N) {
    int t = blockIdx.x * blockDim.x + threadIdx.x;
    if (t >= N * 32) return;
    int n = t >> 5, d = t & 31;
    float ga = g_G[(long)n * 96 + d];
    float gb = g_G[(long)n * 96 + 32 + d];
    float gc = g_G[(long)n * 96 + 64 + d];
    float s0 = ga / (1.f + __expf(-ga));
    float s1 = gb / (1.f + __expf(-gb));
    float s2 = gc / (1.f + __expf(-gc));
    out[t] = node0[t] + s0;
    long base1 = (long)N * 32;
    #pragma unroll
    for (int a = 0; a < 3; a++)
        out[base1 + (long)t * 3 + a] =
            node1[(long)t * 3 + a] + g_Y1[((long)n * 3 + a) * 32 + d] * s1;
    long base2 = (long)N * 128;
    #pragma unroll
    for (int sdx = 0; sdx < 9; sdx++)
        out[base2 + (long)t * 9 + sdx] =
            node2[(long)t * 9 + sdx] + g_Y2[((long)n * 9 + sdx) * 32 + d] * s2;
}

// ---------------- launch ----------------------------------------------------
extern "C" void kernel_launch(void* const* d_in, const int* in_sizes, int n_in,
                              void* d_out, int out_size) {
    const float* node0 = (const float*)d_in[0];
    const float* node1 = (const float*)d_in[1];
    const float* node2 = (const float*)d_in[2];
    const float* rij   = (const float*)d_in[3];
    const float* Wrad  = (const float*)d_in[4];
    const float* U     = (const float*)d_in[5];
    const float* V     = (const float*)d_in[6];
    const float* Wg    = (const float*)d_in[7];
    const int*   idx_i = (const int*)d_in[8];
    const int*   idx_j = (const int*)d_in[9];
    float* out = (float*)d_out;

    int N = in_sizes[0] / 32;
    int E = in_sizes[8];

    void *pF0, *pF1, *pF2, *pY0, *pG, *pY1, *pY2, *pB0, *pB1, *pB2, *pBg;
    cudaGetSymbolAddress(&pF0, g_F0);
    cudaGetSymbolAddress(&pF1, g_F1);
    cudaGetSymbolAddress(&pF2, g_F2);
    cudaGetSymbolAddress(&pY0, g_Y0);
    cudaGetSymbolAddress(&pG,  g_G);
    cudaGetSymbolAddress(&pY1, g_Y1);
    cudaGetSymbolAddress(&pY2, g_Y2);
    cudaGetSymbolAddress(&pB0, g_B0);
    cudaGetSymbolAddress(&pB1, g_B1);
    cudaGetSymbolAddress(&pB2, g_B2);
    cudaGetSymbolAddress(&pBg, g_Bg);

    int nc_blocks = (N * 32 + 255) / 256;

    pack_weights<<<4, 256>>>(U, V, Wg);
    prep_kernel<<<nc_blocks, 256>>>(node0, node1, node2, N);
    edge_kernel<<<1480, 256>>>(rij, Wrad, idx_i, idx_j, E);
    feat_kernel<<<nc_blocks, 256>>>(N);
    // y0 = F0 @ B0
    gemm_kernel<<<dim3((N + 127) / 128, 1), 256>>>((const float*)pF0, (const float*)pB0,
                                                   (float*)pY0, N, 128, 32);
    // gate = y0 @ [Wg0|Wg1|Wg2]
    gemm_kernel<<<dim3((N + 127) / 128, 3), 256>>>((const float*)pY0, (const float*)pBg,
                                                   (float*)pG, N, 32, 96);
    // y1 = F1 @ B1
    gemm_kernel<<<dim3((3 * N + 127) / 128, 1), 256>>>((const float*)pF1, (const float*)pB1,
                                                       (float*)pY1, 3 * N, 96, 32);
    // y2 = F2 @ B2
    gemm_kernel<<<dim3((9 * N + 127) / 128, 1), 256>>>((const float*)pF2, (const float*)pB2,
                                                       (float*)pY2, 9 * N, 128, 32);
    final_kernel<<<nc_blocks, 256>>>(node0, node1, node2, out, N);
}

// round 2
// speedup vs baseline: 1.1439x; 1.1439x over previous
#include <cuda_runtime.h>
#include <math.h>

#define NMAX 20000
#define EMAX 320000

// ---------------- scratch (device globals; no runtime allocation) ----------
__device__ float g_packed[NMAX * 32 * 16];   // per (n,c): [g0, g1[3], g2[9], pad3]
__device__ float g_acc[NMAX * 32 * 16];      // accumulated messages, same layout
__device__ float g_F0[NMAX * 128];           // features for y0 GEMM
__device__ float g_F1[NMAX * 3 * 96];        // features for y1 GEMM
__device__ float g_F2[NMAX * 9 * 128];       // features for y2 GEMM
__device__ float g_G [NMAX * 96];            // gate pre-activations
__device__ float g_Y1[NMAX * 3 * 32];
__device__ float g_Y2[NMAX * 9 * 32];
__device__ float g_B0[128 * 32];             // stacked [U0;V0;V3;V6]
__device__ float g_B1[96 * 32];              // stacked [U1;V1;V5]
__device__ float g_B2[128 * 32];             // stacked [U2;V2;V4;V7]
__device__ float g_Bg[32 * 96];              // [Wg0|Wg1|Wg2]
__device__ float2 g_W2[48 * 32];             // packed radial weights [b(8)][q(6)][c(32)]
                                             // pair q -> paths (2q, 2q+1), pre-scaled by exp(-4(delta*b)^2)

#define RBF_DELTA 0.6428571429f              // (5.0-0.5)/7

// ---------------- helpers ---------------------------------------------------
__device__ __forceinline__ void red_add_v4(float* addr, float x, float y, float z, float w) {
    asm volatile(
        "{\n\t"
        ".reg .u64 a;\n\t"
        "cvta.to.global.u64 a, %0;\n\t"
        "red.global.add.v4.f32 [a], {%1, %2, %3, %4};\n\t"
        "}"
        :: "l"(addr), "f"(x), "f"(y), "f"(z), "f"(w) : "memory");
}
__device__ __forceinline__ void red_add_f32(float* addr, float x) {
    asm volatile(
        "{\n\t"
        ".reg .u64 a;\n\t"
        "cvta.to.global.u64 a, %0;\n\t"
        "red.global.add.f32 [a], %1;\n\t"
        "}"
        :: "l"(addr), "f"(x) : "memory");
}
__device__ __forceinline__ void ffma2(unsigned long long& d, unsigned long long a,
                                      unsigned long long b) {
    asm("fma.rn.f32x2 %0, %1, %2, %0;" : "+l"(d) : "l"(a), "l"(b));
}
__device__ __forceinline__ unsigned long long pack2(float lo, float hi) {
    unsigned long long r;
    asm("mov.b64 %0, {%1, %2};" : "=l"(r) : "f"(lo), "f"(hi));
    return r;
}
__device__ __forceinline__ void unpack2(unsigned long long v, float& lo, float& hi) {
    asm("mov.b64 {%0, %1}, %2;" : "=f"(lo), "=f"(hi) : "l"(v));
}

// ---------------- kernel 0: pack stacked weight matrices -------------------
__global__ void pack_weights(const float* __restrict__ U, const float* __restrict__ V,
                             const float* __restrict__ Wg, const float* __restrict__ Wrad) {
    int t = blockIdx.x * blockDim.x + threadIdx.x;
    if (t < 1024) {
        int c = t >> 5, d = t & 31;
        int cd = c * 32 + d;
        g_B0[t]        = U[cd];
        g_B0[1024 + t] = V[cd];
        g_B0[2048 + t] = V[3072 + cd];
        g_B0[3072 + t] = V[6144 + cd];
        g_B1[t]        = U[1024 + cd];
        g_B1[1024 + t] = V[1024 + cd];
        g_B1[2048 + t] = V[5120 + cd];
        g_B2[t]        = U[2048 + cd];
        g_B2[1024 + t] = V[2048 + cd];
        g_B2[2048 + t] = V[4096 + cd];
        g_B2[3072 + t] = V[7168 + cd];
        g_Bg[c * 96 + d]      = Wg[cd];
        g_Bg[c * 96 + 32 + d] = Wg[1024 + cd];
        g_Bg[c * 96 + 64 + d] = Wg[2048 + cd];
    }
    // packed radial weights: 48 pair-slots x 32 channels
    if (t < 1536) {
        int k = t >> 5, c = t & 31;
        int b = k / 6, q = k % 6;
        float db = RBF_DELTA * (float)b;
        float scale = expf(-4.f * db * db);
        int p0 = 2 * q, p1 = 2 * q + 1;
        float lo = Wrad[(p0 * 8 + b) * 32 + c] * scale;
        float hi = (p1 < 11) ? Wrad[(p1 * 8 + b) * 32 + c] * scale : 0.f;
        g_W2[k * 32 + c] = make_float2(lo, hi);
    }
}

// ---------------- kernel 1: repack node features + zero accumulator --------
__global__ void prep_kernel(const float* __restrict__ node0, const float* __restrict__ node1,
                            const float* __restrict__ node2, int N) {
    int t = blockIdx.x * blockDim.x + threadIdx.x;
    if (t >= N * 32) return;
    const float* p1 = &node1[(long)t * 3];
    const float* p2 = &node2[(long)t * 9];
    float4 o0 = make_float4(node0[t], p1[0], p1[1], p1[2]);
    float4 o1 = make_float4(p2[0], p2[1], p2[2], p2[3]);
    float4 o2 = make_float4(p2[4], p2[5], p2[6], p2[7]);
    float4 o3 = make_float4(p2[8], 0.f, 0.f, 0.f);
    float4* dp = (float4*)&g_packed[(long)t * 16];
    dp[0] = o0; dp[1] = o1; dp[2] = o2; dp[3] = o3;
    float4 z = make_float4(0.f, 0.f, 0.f, 0.f);
    float4* da = (float4*)&g_acc[(long)t * 16];
    da[0] = z; da[1] = z; da[2] = z; da[3] = z;
}

// ---------------- kernel 2: edge messages + scatter -------------------------
// One warp per edge, lane = channel. Radial weights live in 96 registers/lane.
// rbf_b = base * rho^b with constants folded into g_W2; filter accumulated in
// packed f32x2 (48 FFMA2 instead of 88 LDS+FFMA).
__global__ void __launch_bounds__(128, 3)
edge_kernel(const float* __restrict__ rij,
            const int* __restrict__ idx_i, const int* __restrict__ idx_j, int E) {
    int lane = threadIdx.x & 31;
    int warp = threadIdx.x >> 5;
    unsigned long long Wreg[48];
    const unsigned long long* wsrc = (const unsigned long long*)g_W2;
    #pragma unroll
    for (int k = 0; k < 48; k++) Wreg[k] = wsrc[k * 32 + lane];

    int gw = blockIdx.x * 4 + warp;
    int stride = gridDim.x * 4;
    for (int e = gw; e < E; e += stride) {
        float rx = __ldg(&rij[e * 3 + 0]);
        float ry = __ldg(&rij[e * 3 + 1]);
        float rz = __ldg(&rij[e * 3 + 2]);
        int ii = __ldg(&idx_i[e]);
        int jj = __ldg(&idx_j[e]);
        float d2 = rx * rx + ry * ry + rz * rz + 1e-12f;
        float inv = rsqrtf(d2);
        float dist = d2 * inv;
        rx *= inv; ry *= inv; rz *= inv;
        float u = dist - 0.5f;
        float xx = fminf(dist * 0.2f, 1.0f);
        float fc = 0.5f * (__cosf(3.14159265358979f * xx) + 1.0f);
        float base = __expf(-4.f * u * u) * fc;
        float rho = __expf(fminf(8.f * RBF_DELTA * u, 80.f));

        unsigned long long wv[6];
        #pragma unroll
        for (int q = 0; q < 6; q++) wv[q] = 0ull;
        float t = base;
        #pragma unroll
        for (int b = 0; b < 8; b++) {
            unsigned long long tb = pack2(t, t);
            #pragma unroll
            for (int q = 0; q < 6; q++) ffma2(wv[q], tb, Wreg[b * 6 + q]);
            t *= rho;
        }
        float w[12];
        #pragma unroll
        for (int q = 0; q < 6; q++) unpack2(wv[q], w[2 * q], w[2 * q + 1]);

        // gather node_j features (13 used floats of the 16-float slot)
        const float* srcf = &g_packed[((long)jj * 32 + lane) * 16];
        float4 q0 = *(const float4*)(srcf + 0);
        float4 q1 = *(const float4*)(srcf + 4);
        float4 q2 = *(const float4*)(srcf + 8);
        float q3x = __ldg(srcf + 12);
        float g0 = q0.x, g1x = q0.y, g1y = q0.z, g1z = q0.w;
        float s1 = g1x * rx + g1y * ry + g1z * rz;
        float v2x = q1.x * rx + q1.y * ry + q1.z * rz;
        float v2y = q1.w * rx + q2.x * ry + q2.y * rz;
        float v2z = q2.z * rx + q2.w * ry + q3x * rz;
        float s2 = v2x * rx + v2y * ry + v2z * rz;
        // msg0
        float msg0 = g0 * w[0] + s1 * w[4] + s2 * w[9];
        // msg1[a] = (g0 w1 + s1 w6) r_a + w3 g1_a + w8 v2_a
        float cc = g0 * w[1] + s1 * w[6];
        float m1x = cc * rx + g1x * w[3] + w[8] * v2x;
        float m1y = cc * ry + g1y * w[3] + w[8] * v2y;
        float m1z = cc * rz + g1z * w[3] + w[8] * v2z;
        // msg2[ab] = w7 g2_ab + (g0 w2 r_a + w5 g1_a + w10 v2_a) r_b
        float g0w2 = g0 * w[2];
        float pax = g0w2 * rx + w[5] * g1x + w[10] * v2x;
        float pay = g0w2 * ry + w[5] * g1y + w[10] * v2y;
        float paz = g0w2 * rz + w[5] * g1z + w[10] * v2z;
        float* dst = &g_acc[((long)ii * 32 + lane) * 16];
        red_add_v4(dst + 0, msg0, m1x, m1y, m1z);
        red_add_v4(dst + 4,
                   w[7] * q1.x + pax * rx, w[7] * q1.y + pax * ry,
                   w[7] * q1.z + pax * rz, w[7] * q1.w + pay * rx);
        red_add_v4(dst + 8,
                   w[7] * q2.x + pay * ry, w[7] * q2.y + pay * rz,
                   w[7] * q2.z + paz * rx, w[7] * q2.w + paz * ry);
        red_add_f32(dst + 12, w[7] * q3x + paz * rz);
    }
}

// ---------------- kernel 3: build GEMM feature matrices --------------------
__global__ void feat_kernel(int N) {
    int t = blockIdx.x * blockDim.x + threadIdx.x;
    if (t >= N * 32) return;
    int n = t >> 5, c = t & 31;
    const float4* src = (const float4*)&g_acc[(long)t * 16];
    float4 q0 = src[0], q1 = src[1], q2 = src[2], q3 = src[3];
    const float s = 1.f / 16.f;   // NORM_FACTOR
    float a0 = q0.x * s;
    float a1[3] = {q0.y * s, q0.z * s, q0.w * s};
    float a2[9] = {q1.x * s, q1.y * s, q1.z * s, q1.w * s,
                   q2.x * s, q2.y * s, q2.z * s, q2.w * s, q3.x * s};
    float* f0 = &g_F0[(long)n * 128];
    f0[c]      = a0;
    f0[32 + c] = a0 * a0;
    f0[64 + c] = a1[0] * a1[0] + a1[1] * a1[1] + a1[2] * a1[2];
    float s22 = 0.f;
    #pragma unroll
    for (int i = 0; i < 9; i++) s22 += a2[i] * a2[i];
    f0[96 + c] = s22;
    #pragma unroll
    for (int a = 0; a < 3; a++) {
        float* f1 = &g_F1[((long)n * 3 + a) * 96];
        f1[c]      = a1[a];
        f1[32 + c] = a0 * a1[a];
        f1[64 + c] = a1[0] * a2[a] + a1[1] * a2[3 + a] + a1[2] * a2[6 + a];
    }
    #pragma unroll
    for (int a = 0; a < 3; a++) {
        #pragma unroll
        for (int b = 0; b < 3; b++) {
            int sidx = a * 3 + b;
            float* f2 = &g_F2[((long)n * 9 + sidx) * 128];
            f2[c]      = a2[sidx];
            f2[32 + c] = a0 * a2[sidx];
            f2[64 + c] = a1[a] * a1[b];
            f2[96 + c] = a2[a * 3 + 0] * a2[b] + a2[a * 3 + 1] * a2[3 + b]
                       + a2[a * 3 + 2] * a2[6 + b];
        }
    }
}

// ---------------- kernel 4: tiled fp32 GEMM  C[M,NC] = A[M,K] @ B[K,NC] ----
__global__ void gemm_kernel(const float* __restrict__ A, const float* __restrict__ B,
                            float* __restrict__ Cmat, int M, int K, int NC) {
    __shared__ float sA[128 * 33];
    __shared__ float sB[32 * 32];
    int tid = threadIdx.x;
    int m0 = blockIdx.x * 128;
    int cblk = blockIdx.y * 32;
    int dg = tid & 7, rg = tid >> 3;
    int c0 = dg * 4, r0 = rg * 4;
    float acc[4][4] = {};
    for (int kc = 0; kc < K; kc += 32) {
        for (int idx = tid; idx < 128 * 32; idx += 256) {
            int r = idx >> 5, kk = idx & 31;
            int m = m0 + r;
            sA[r * 33 + kk] = (m < M) ? A[(long)m * K + kc + kk] : 0.f;
        }
        for (int idx = tid; idx < 32 * 32; idx += 256) {
            int kk = idx >> 5, d = idx & 31;
            sB[kk * 32 + d] = B[(long)(kc + kk) * NC + cblk + d];
        }
        __syncthreads();
        #pragma unroll
        for (int kk = 0; kk < 32; kk++) {
            float4 b4 = *(const float4*)&sB[kk * 32 + c0];
            #pragma unroll
            for (int i = 0; i < 4; i++) {
                float a = sA[(r0 + i) * 33 + kk];
                acc[i][0] += a * b4.x;
                acc[i][1] += a * b4.y;
                acc[i][2] += a * b4.z;
                acc[i][3] += a * b4.w;
            }
        }
        __syncthreads();
    }
    #pragma unroll
    for (int i = 0; i < 4; i++) {
        int m = m0 + r0 + i;
        if (m < M) {
            float4 v = make_float4(acc[i][0], acc[i][1], acc[i][2], acc[i][3]);
            *(float4*)&Cmat[(long)m * NC + cblk + c0] = v;
        }
    }
}

// ---------------- kernel 4b: fused y0 GEMM + gate GEMM ---------------------
// stage 1: y0 = F0[128 rows x 128] @ B0[128 x 32]  (kept in smem only)
// stage 2: G  = y0 @ Bg[32 x 96]                    (written to g_G)
__global__ void y0gate_kernel(const float* __restrict__ F0, int N) {
    __shared__ float sA[128 * 33];
    __shared__ float sB[32 * 32];
    __shared__ float sY[128 * 33];
    int tid = threadIdx.x;
    int m0 = blockIdx.x * 128;
    int dg = tid & 7, rg = tid >> 3;
    int c0 = dg * 4, r0 = rg * 4;
    float acc[4][4] = {};
    for (int kc = 0; kc < 128; kc += 32) {
        for (int idx = tid; idx < 128 * 32; idx += 256) {
            int r = idx >> 5, kk = idx & 31;
            int m = m0 + r;
            sA[r * 33 + kk] = (m < N) ? F0[(long)m * 128 + kc + kk] : 0.f;
        }
        for (int idx = tid; idx < 32 * 32; idx += 256) {
            int kk = idx >> 5, d = idx & 31;
            sB[kk * 32 + d] = g_B0[(kc + kk) * 32 + d];
        }
        __syncthreads();
        #pragma unroll
        for (int kk = 0; kk < 32; kk++) {
            float4 b4 = *(const float4*)&sB[kk * 32 + c0];
            #pragma unroll
            for (int i = 0; i < 4; i++) {
                float a = sA[(r0 + i) * 33 + kk];
                acc[i][0] += a * b4.x;
                acc[i][1] += a * b4.y;
                acc[i][2] += a * b4.z;
                acc[i][3] += a * b4.w;
            }
        }
        __syncthreads();
    }
    // stash y0 tile in shared
    #pragma unroll
    for (int i = 0; i < 4; i++) {
        #pragma unroll
        for (int j = 0; j < 4; j++) sY[(r0 + i) * 33 + c0 + j] = acc[i][j];
    }
    __syncthreads();
    // stage 2: three 32-column segments of the gate matrix
    for (int seg = 0; seg < 3; seg++) {
        for (int idx = tid; idx < 32 * 32; idx += 256) {
            int kk = idx >> 5, d = idx & 31;
            sB[kk * 32 + d] = g_Bg[kk * 96 + seg * 32 + d];
        }
        __syncthreads();
        float acc2[4][4] = {};
        #pragma unroll
        for (int kk = 0; kk < 32; kk++) {
            float4 b4 = *(const float4*)&sB[kk * 32 + c0];
            #pragma unroll
            for (int i = 0; i < 4; i++) {
                float a = sY[(r0 + i) * 33 + kk];
                acc2[i][0] += a * b4.x;
                acc2[i][1] += a * b4.y;
                acc2[i][2] += a * b4.z;
                acc2[i][3] += a * b4.w;
            }
        }
        #pragma unroll
        for (int i = 0; i < 4; i++) {
            int m = m0 + r0 + i;
            if (m < N) {
                float4 v = make_float4(acc2[i][0], acc2[i][1], acc2[i][2], acc2[i][3]);
                *(float4*)&g_G[(long)m * 96 + seg * 32 + c0] = v;
            }
        }
        __syncthreads();
    }
}

// ---------------- kernel 5: gated nonlinearity + residual ------------------
__global__ void final_kernel(const float* __restrict__ node0, const float* __restrict__ node1,
                             const float* __restrict__ node2, float* __restrict__ out, int N) {
    int t = blockIdx.x * blockDim.x + threadIdx.x;
    if (t >= N * 32) return;
    int n = t >> 5, d = t & 31;
    float ga = g_G[(long)n * 96 + d];
    float gb = g_G[(long)n * 96 + 32 + d];
    float gc = g_G[(long)n * 96 + 64 + d];
    float s0 = ga / (1.f + __expf(-ga));
    float s1 = gb / (1.f + __expf(-gb));
    float s2 = gc / (1.f + __expf(-gc));
    out[t] = node0[t] + s0;
    long base1 = (long)N * 32;
    #pragma unroll
    for (int a = 0; a < 3; a++)
        out[base1 + (long)t * 3 + a] =
            node1[(long)t * 3 + a] + g_Y1[((long)n * 3 + a) * 32 + d] * s1;
    long base2 = (long)N * 128;
    #pragma unroll
    for (int sdx = 0; sdx < 9; sdx++)
        out[base2 + (long)t * 9 + sdx] =
            node2[(long)t * 9 + sdx] + g_Y2[((long)n * 9 + sdx) * 32 + d] * s2;
}

// ---------------- launch ----------------------------------------------------
extern "C" void kernel_launch(void* const* d_in, const int* in_sizes, int n_in,
                              void* d_out, int out_size) {
    const float* node0 = (const float*)d_in[0];
    const float* node1 = (const float*)d_in[1];
    const float* node2 = (const float*)d_in[2];
    const float* rij   = (const float*)d_in[3];
    const float* Wrad  = (const float*)d_in[4];
    const float* U     = (const float*)d_in[5];
    const float* V     = (const float*)d_in[6];
    const float* Wg    = (const float*)d_in[7];
    const int*   idx_i = (const int*)d_in[8];
    const int*   idx_j = (const int*)d_in[9];
    float* out = (float*)d_out;

    int N = in_sizes[0] / 32;
    int E = in_sizes[8];

    void *pF0, *pF1, *pF2, *pY1, *pY2, *pB1, *pB2;
    cudaGetSymbolAddress(&pF0, g_F0);
    cudaGetSymbolAddress(&pF1, g_F1);
    cudaGetSymbolAddress(&pF2, g_F2);
    cudaGetSymbolAddress(&pY1, g_Y1);
    cudaGetSymbolAddress(&pY2, g_Y2);
    cudaGetSymbolAddress(&pB1, g_B1);
    cudaGetSymbolAddress(&pB2, g_B2);

    int nc_blocks = (N * 32 + 255) / 256;

    pack_weights<<<8, 256>>>(U, V, Wg, Wrad);
    prep_kernel<<<nc_blocks, 256>>>(node0, node1, node2, N);
    edge_kernel<<<444, 128>>>(rij, idx_i, idx_j, E);
    feat_kernel<<<nc_blocks, 256>>>(N);
    // y0 + gate (fused; y0 never leaves shared memory)
    y0gate_kernel<<<(N + 127) / 128, 256>>>((const float*)pF0, N);
    // y1 = F1 @ B1
    gemm_kernel<<<dim3((3 * N + 127) / 128, 1), 256>>>((const float*)pF1, (const float*)pB1,
                                                       (float*)pY1, 3 * N, 96, 32);
    // y2 = F2 @ B2
    gemm_kernel<<<dim3((9 * N + 127) / 128, 1), 256>>>((const float*)pF2, (const float*)pB2,
                                                       (float*)pY2, 9 * N, 128, 32);
    final_kernel<<<nc_blocks, 256>>>(node0, node1, node2, out, N);
}

// round 3
// speedup vs baseline: 1.1458x; 1.0016x over previous
#include <cuda_runtime.h>
#include <math.h>

#define NMAX 20000
#define EMAX 320000

// ---------------- scratch (device globals; no runtime allocation) ----------
__device__ float g_packed[NMAX * 32 * 16];   // per (n,c): [g0, g1[3], g2[9], pad3]
__device__ float g_acc[NMAX * 32 * 16];      // accumulated messages, same layout
__device__ float g_F0[NMAX * 128];           // features for y0 GEMM
__device__ float g_F1[NMAX * 3 * 96];        // features for y1 GEMM
__device__ float g_F2[NMAX * 9 * 128];       // features for y2 GEMM
__device__ float g_G [NMAX * 96];            // gate pre-activations
__device__ float g_Y1[NMAX * 3 * 32];
__device__ float g_Y2[NMAX * 9 * 32];
__device__ float g_B0[128 * 32];             // stacked [U0;V0;V3;V6]
__device__ float g_B1[96 * 32];              // stacked [U1;V1;V5]
__device__ float g_B2[128 * 32];             // stacked [U2;V2;V4;V7]
__device__ float g_Bg[32 * 96];              // [Wg0|Wg1|Wg2]
__device__ float2 g_W2[48 * 32];             // packed radial weights [b(8)][q(6)][c(32)]
                                             // pair q -> paths (2q, 2q+1), pre-scaled by exp(-4(delta*b)^2)

#define RBF_DELTA 0.6428571429f              // (5.0-0.5)/7

// ---------------- helpers ---------------------------------------------------
__device__ __forceinline__ void red_add_v4(float* addr, float x, float y, float z, float w) {
    asm volatile(
        "{\n\t"
        ".reg .u64 a;\n\t"
        "cvta.to.global.u64 a, %0;\n\t"
        "red.global.add.v4.f32 [a], {%1, %2, %3, %4};\n\t"
        "}"
        :: "l"(addr), "f"(x), "f"(y), "f"(z), "f"(w) : "memory");
}
__device__ __forceinline__ void red_add_f32(float* addr, float x) {
    asm volatile(
        "{\n\t"
        ".reg .u64 a;\n\t"
        "cvta.to.global.u64 a, %0;\n\t"
        "red.global.add.f32 [a], %1;\n\t"
        "}"
        :: "l"(addr), "f"(x) : "memory");
}
__device__ __forceinline__ void ffma2(unsigned long long& d, unsigned long long a,
                                      unsigned long long b) {
    asm("fma.rn.f32x2 %0, %1, %2, %0;" : "+l"(d) : "l"(a), "l"(b));
}
__device__ __forceinline__ unsigned long long pack2(float lo, float hi) {
    unsigned long long r;
    asm("mov.b64 %0, {%1, %2};" : "=l"(r) : "f"(lo), "f"(hi));
    return r;
}
__device__ __forceinline__ void unpack2(unsigned long long v, float& lo, float& hi) {
    asm("mov.b64 {%0, %1}, %2;" : "=f"(lo), "=f"(hi) : "l"(v));
}

// ---------------- kernel 0: pack stacked weight matrices -------------------
__global__ void pack_weights(const float* __restrict__ U, const float* __restrict__ V,
                             const float* __restrict__ Wg, const float* __restrict__ Wrad) {
    int t = blockIdx.x * blockDim.x + threadIdx.x;
    if (t < 1024) {
        int c = t >> 5, d = t & 31;
        int cd = c * 32 + d;
        g_B0[t]        = U[cd];
        g_B0[1024 + t] = V[cd];
        g_B0[2048 + t] = V[3072 + cd];
        g_B0[3072 + t] = V[6144 + cd];
        g_B1[t]        = U[1024 + cd];
        g_B1[1024 + t] = V[1024 + cd];
        g_B1[2048 + t] = V[5120 + cd];
        g_B2[t]        = U[2048 + cd];
        g_B2[1024 + t] = V[2048 + cd];
        g_B2[2048 + t] = V[4096 + cd];
        g_B2[3072 + t] = V[7168 + cd];
        g_Bg[c * 96 + d]      = Wg[cd];
        g_Bg[c * 96 + 32 + d] = Wg[1024 + cd];
        g_Bg[c * 96 + 64 + d] = Wg[2048 + cd];
    }
    // packed radial weights: 48 pair-slots x 32 channels
    if (t < 1536) {
        int k = t >> 5, c = t & 31;
        int b = k / 6, q = k % 6;
        float db = RBF_DELTA * (float)b;
        float scale = expf(-4.f * db * db);
        int p0 = 2 * q, p1 = 2 * q + 1;
        float lo = Wrad[(p0 * 8 + b) * 32 + c] * scale;
        float hi = (p1 < 11) ? Wrad[(p1 * 8 + b) * 32 + c] * scale : 0.f;
        g_W2[k * 32 + c] = make_float2(lo, hi);
    }
}

// ---------------- kernel 1: repack node features + zero accumulator --------
__global__ void prep_kernel(const float* __restrict__ node0, const float* __restrict__ node1,
                            const float* __restrict__ node2, int N) {
    int t = blockIdx.x * blockDim.x + threadIdx.x;
    if (t >= N * 32) return;
    const float* p1 = &node1[(long)t * 3];
    const float* p2 = &node2[(long)t * 9];
    float4 o0 = make_float4(node0[t], p1[0], p1[1], p1[2]);
    float4 o1 = make_float4(p2[0], p2[1], p2[2], p2[3]);
    float4 o2 = make_float4(p2[4], p2[5], p2[6], p2[7]);
    float4 o3 = make_float4(p2[8], 0.f, 0.f, 0.f);
    float4* dp = (float4*)&g_packed[(long)t * 16];
    dp[0] = o0; dp[1] = o1; dp[2] = o2; dp[3] = o3;
    float4 z = make_float4(0.f, 0.f, 0.f, 0.f);
    float4* da = (float4*)&g_acc[(long)t * 16];
    da[0] = z; da[1] = z; da[2] = z; da[3] = z;
}

// ---------------- kernel 2: edge messages + scatter -------------------------
// One warp per edge, lane = channel. Radial weights live in 96 registers/lane.
// rbf_b = base * rho^b with constants folded into g_W2; filter accumulated in
// packed f32x2 (48 FFMA2 instead of 88 LDS+FFMA).
__global__ void __launch_bounds__(128, 3)
edge_kernel(const float* __restrict__ rij,
            const int* __restrict__ idx_i, const int* __restrict__ idx_j, int E) {
    int lane = threadIdx.x & 31;
    int warp = threadIdx.x >> 5;
    unsigned long long Wreg[48];
    const unsigned long long* wsrc = (const unsigned long long*)g_W2;
    #pragma unroll
    for (int k = 0; k < 48; k++) Wreg[k] = wsrc[k * 32 + lane];

    int gw = blockIdx.x * 4 + warp;
    int stride = gridDim.x * 4;
    for (int e = gw; e < E; e += stride) {
        float rx = __ldg(&rij[e * 3 + 0]);
        float ry = __ldg(&rij[e * 3 + 1]);
        float rz = __ldg(&rij[e * 3 + 2]);
        int ii = __ldg(&idx_i[e]);
        int jj = __ldg(&idx_j[e]);
        float d2 = rx * rx + ry * ry + rz * rz + 1e-12f;
        float inv = rsqrtf(d2);
        float dist = d2 * inv;
        rx *= inv; ry *= inv; rz *= inv;
        float u = dist - 0.5f;
        float xx = fminf(dist * 0.2f, 1.0f);
        float fc = 0.5f * (__cosf(3.14159265358979f * xx) + 1.0f);
        float base = __expf(-4.f * u * u) * fc;
        float rho = __expf(fminf(8.f * RBF_DELTA * u, 80.f));

        unsigned long long wv[6];
        #pragma unroll
        for (int q = 0; q < 6; q++) wv[q] = 0ull;
        float t = base;
        #pragma unroll
        for (int b = 0; b < 8; b++) {
            unsigned long long tb = pack2(t, t);
            #pragma unroll
            for (int q = 0; q < 6; q++) ffma2(wv[q], tb, Wreg[b * 6 + q]);
            t *= rho;
        }
        float w[12];
        #pragma unroll
        for (int q = 0; q < 6; q++) unpack2(wv[q], w[2 * q], w[2 * q + 1]);

        // gather node_j features (13 used floats of the 16-float slot)
        const float* srcf = &g_packed[((long)jj * 32 + lane) * 16];
        float4 q0 = *(const float4*)(srcf + 0);
        float4 q1 = *(const float4*)(srcf + 4);
        float4 q2 = *(const float4*)(srcf + 8);
        float q3x = __ldg(srcf + 12);
        float g0 = q0.x, g1x = q0.y, g1y = q0.z, g1z = q0.w;
        float s1 = g1x * rx + g1y * ry + g1z * rz;
        float v2x = q1.x * rx + q1.y * ry + q1.z * rz;
        float v2y = q1.w * rx + q2.x * ry + q2.y * rz;
        float v2z = q2.z * rx + q2.w * ry + q3x * rz;
        float s2 = v2x * rx + v2y * ry + v2z * rz;
        // msg0
        float msg0 = g0 * w[0] + s1 * w[4] + s2 * w[9];
        // msg1[a] = (g0 w1 + s1 w6) r_a + w3 g1_a + w8 v2_a
        float cc = g0 * w[1] + s1 * w[6];
        float m1x = cc * rx + g1x * w[3] + w[8] * v2x;
        float m1y = cc * ry + g1y * w[3] + w[8] * v2y;
        float m1z = cc * rz + g1z * w[3] + w[8] * v2z;
        // msg2[ab] = w7 g2_ab + (g0 w2 r_a + w5 g1_a + w10 v2_a) r_b
        float g0w2 = g0 * w[2];
        float pax = g0w2 * rx + w[5] * g1x + w[10] * v2x;
        float pay = g0w2 * ry + w[5] * g1y + w[10] * v2y;
        float paz = g0w2 * rz + w[5] * g1z + w[10] * v2z;
        float* dst = &g_acc[((long)ii * 32 + lane) * 16];
        red_add_v4(dst + 0, msg0, m1x, m1y, m1z);
        red_add_v4(dst + 4,
                   w[7] * q1.x + pax * rx, w[7] * q1.y + pax * ry,
                   w[7] * q1.z + pax * rz, w[7] * q1.w + pay * rx);
        red_add_v4(dst + 8,
                   w[7] * q2.x + pay * ry, w[7] * q2.y + pay * rz,
                   w[7] * q2.z + paz * rx, w[7] * q2.w + paz * ry);
        red_add_f32(dst + 12, w[7] * q3x + paz * rz);
    }
}

// ---------------- kernel 3: build GEMM feature matrices --------------------
__global__ void feat_kernel(int N) {
    int t = blockIdx.x * blockDim.x + threadIdx.x;
    if (t >= N * 32) return;
    int n = t >> 5, c = t & 31;
    const float4* src = (const float4*)&g_acc[(long)t * 16];
    float4 q0 = src[0], q1 = src[1], q2 = src[2], q3 = src[3];
    const float s = 1.f / 16.f;   // NORM_FACTOR
    float a0 = q0.x * s;
    float a1[3] = {q0.y * s, q0.z * s, q0.w * s};
    float a2[9] = {q1.x * s, q1.y * s, q1.z * s, q1.w * s,
                   q2.x * s, q2.y * s, q2.z * s, q2.w * s, q3.x * s};
    float* f0 = &g_F0[(long)n * 128];
    f0[c]      = a0;
    f0[32 + c] = a0 * a0;
    f0[64 + c] = a1[0] * a1[0] + a1[1] * a1[1] + a1[2] * a1[2];
    float s22 = 0.f;
    #pragma unroll
    for (int i = 0; i < 9; i++) s22 += a2[i] * a2[i];
    f0[96 + c] = s22;
    #pragma unroll
    for (int a = 0; a < 3; a++) {
        float* f1 = &g_F1[((long)n * 3 + a) * 96];
        f1[c]      = a1[a];
        f1[32 + c] = a0 * a1[a];
        f1[64 + c] = a1[0] * a2[a] + a1[1] * a2[3 + a] + a1[2] * a2[6 + a];
    }
    #pragma unroll
    for (int a = 0; a < 3; a++) {
        #pragma unroll
        for (int b = 0; b < 3; b++) {
            int sidx = a * 3 + b;
            float* f2 = &g_F2[((long)n * 9 + sidx) * 128];
            f2[c]      = a2[sidx];
            f2[32 + c] = a0 * a2[sidx];
            f2[64 + c] = a1[a] * a1[b];
            f2[96 + c] = a2[a * 3 + 0] * a2[b] + a2[a * 3 + 1] * a2[3 + b]
                       + a2[a * 3 + 2] * a2[6 + b];
        }
    }
}

// ---------------- kernel 4: tiled fp32 GEMM  C[M,NC] = A[M,K] @ B[K,NC] ----
__global__ void gemm_kernel(const float* __restrict__ A, const float* __restrict__ B,
                            float* __restrict__ Cmat, int M, int K, int NC) {
    __shared__ float sA[128 * 33];
    __shared__ float sB[32 * 32];
    int tid = threadIdx.x;
    int m0 = blockIdx.x * 128;
    int cblk = blockIdx.y * 32;
    int dg = tid & 7, rg = tid >> 3;
    int c0 = dg * 4, r0 = rg * 4;
    float acc[4][4] = {};
    for (int kc = 0; kc < K; kc += 32) {
        for (int idx = tid; idx < 128 * 32; idx += 256) {
            int r = idx >> 5, kk = idx & 31;
            int m = m0 + r;
            sA[r * 33 + kk] = (m < M) ? A[(long)m * K + kc + kk] : 0.f;
        }
        for (int idx = tid; idx < 32 * 32; idx += 256) {
            int kk = idx >> 5, d = idx & 31;
            sB[kk * 32 + d] = B[(long)(kc + kk) * NC + cblk + d];
        }
        __syncthreads();
        #pragma unroll
        for (int kk = 0; kk < 32; kk++) {
            float4 b4 = *(const float4*)&sB[kk * 32 + c0];
            #pragma unroll
            for (int i = 0; i < 4; i++) {
                float a = sA[(r0 + i) * 33 + kk];
                acc[i][0] += a * b4.x;
                acc[i][1] += a * b4.y;
                acc[i][2] += a * b4.z;
                acc[i][3] += a * b4.w;
            }
        }
        __syncthreads();
    }
    #pragma unroll
    for (int i = 0; i < 4; i++) {
        int m = m0 + r0 + i;
        if (m < M) {
            float4 v = make_float4(acc[i][0], acc[i][1], acc[i][2], acc[i][3]);
            *(float4*)&Cmat[(long)m * NC + cblk + c0] = v;
        }
    }
}

// ---------------- kernel 4b: fused y0 GEMM + gate GEMM ---------------------
// stage 1: y0 = F0[128 rows x 128] @ B0[128 x 32]  (kept in smem only)
// stage 2: G  = y0 @ Bg[32 x 96]                    (written to g_G)
__global__ void y0gate_kernel(const float* __restrict__ F0, int N) {
    __shared__ float sA[128 * 33];
    __shared__ float sB[32 * 32];
    __shared__ float sY[128 * 33];
    int tid = threadIdx.x;
    int m0 = blockIdx.x * 128;
    int dg = tid & 7, rg = tid >> 3;
    int c0 = dg * 4, r0 = rg * 4;
    float acc[4][4] = {};
    for (int kc = 0; kc < 128; kc += 32) {
        for (int idx = tid; idx < 128 * 32; idx += 256) {
            int r = idx >> 5, kk = idx & 31;
            int m = m0 + r;
            sA[r * 33 + kk] = (m < N) ? F0[(long)m * 128 + kc + kk] : 0.f;
        }
        for (int idx = tid; idx < 32 * 32; idx += 256) {
            int kk = idx >> 5, d = idx & 31;
            sB[kk * 32 + d] = g_B0[(kc + kk) * 32 + d];
        }
        __syncthreads();
        #pragma unroll
        for (int kk = 0; kk < 32; kk++) {
            float4 b4 = *(const float4*)&sB[kk * 32 + c0];
            #pragma unroll
            for (int i = 0; i < 4; i++) {
                float a = sA[(r0 + i) * 33 + kk];
                acc[i][0] += a * b4.x;
                acc[i][1] += a * b4.y;
                acc[i][2] += a * b4.z;
                acc[i][3] += a * b4.w;
            }
        }
        __syncthreads();
    }
    // stash y0 tile in shared
    #pragma unroll
    for (int i = 0; i < 4; i++) {
        #pragma unroll
        for (int j = 0; j < 4; j++) sY[(r0 + i) * 33 + c0 + j] = acc[i][j];
    }
    __syncthreads();
    // stage 2: three 32-column segments of the gate matrix
    for (int seg = 0; seg < 3; seg++) {
        for (int idx = tid; idx < 32 * 32; idx += 256) {
            int kk = idx >> 5, d = idx & 31;
            sB[kk * 32 + d] = g_Bg[kk * 96 + seg * 32 + d];
        }
        __syncthreads();
        float acc2[4][4] = {};
        #pragma unroll
        for (int kk = 0; kk < 32; kk++) {
            float4 b4 = *(const float4*)&sB[kk * 32 + c0];
            #pragma unroll
            for (int i = 0; i < 4; i++) {
                float a = sY[(r0 + i) * 33 + kk];
                acc2[i][0] += a * b4.x;
                acc2[i][1] += a * b4.y;
                acc2[i][2] += a * b4.z;
                acc2[i][3] += a * b4.w;
            }
        }
        #pragma unroll
        for (int i = 0; i < 4; i++) {
            int m = m0 + r0 + i;
            if (m < N) {
                float4 v = make_float4(acc2[i][0], acc2[i][1], acc2[i][2], acc2[i][3]);
                *(float4*)&g_G[(long)m * 96 + seg * 32 + c0] = v;
            }
        }
        __syncthreads();
    }
}

// ---------------- kernel 5: gated nonlinearity + residual ------------------
__global__ void final_kernel(const float* __restrict__ node0, const float* __restrict__ node1,
                             const float* __restrict__ node2, float* __restrict__ out, int N) {
    int t = blockIdx.x * blockDim.x + threadIdx.x;
    if (t >= N * 32) return;
    int n = t >> 5, d = t & 31;
    float ga = g_G[(long)n * 96 + d];
    float gb = g_G[(long)n * 96 + 32 + d];
    float gc = g_G[(long)n * 96 + 64 + d];
    float s0 = ga / (1.f + __expf(-ga));
    float s1 = gb / (1.f + __expf(-gb));
    float s2 = gc / (1.f + __expf(-gc));
    out[t] = node0[t] + s0;
    long base1 = (long)N * 32;
    #pragma unroll
    for (int a = 0; a < 3; a++)
        out[base1 + (long)t * 3 + a] =
            node1[(long)t * 3 + a] + g_Y1[((long)n * 3 + a) * 32 + d] * s1;
    long base2 = (long)N * 128;
    #pragma unroll
    for (int sdx = 0; sdx < 9; sdx++)
        out[base2 + (long)t * 9 + sdx] =
            node2[(long)t * 9 + sdx] + g_Y2[((long)n * 9 + sdx) * 32 + d] * s2;
}

// ---------------- launch ----------------------------------------------------
extern "C" void kernel_launch(void* const* d_in, const int* in_sizes, int n_in,
                              void* d_out, int out_size) {
    const float* node0 = (const float*)d_in[0];
    const float* node1 = (const float*)d_in[1];
    const float* node2 = (const float*)d_in[2];
    const float* rij   = (const float*)d_in[3];
    const float* Wrad  = (const float*)d_in[4];
    const float* U     = (const float*)d_in[5];
    const float* V     = (const float*)d_in[6];
    const float* Wg    = (const float*)d_in[7];
    const int*   idx_i = (const int*)d_in[8];
    const int*   idx_j = (const int*)d_in[9];
    float* out = (float*)d_out;

    int N = in_sizes[0] / 32;
    int E = in_sizes[8];

    void *pF0, *pF1, *pF2, *pY1, *pY2, *pB1, *pB2;
    cudaGetSymbolAddress(&pF0, g_F0);
    cudaGetSymbolAddress(&pF1, g_F1);
    cudaGetSymbolAddress(&pF2, g_F2);
    cudaGetSymbolAddress(&pY1, g_Y1);
    cudaGetSymbolAddress(&pY2, g_Y2);
    cudaGetSymbolAddress(&pB1, g_B1);
    cudaGetSymbolAddress(&pB2, g_B2);

    int nc_blocks = (N * 32 + 255) / 256;

    pack_weights<<<8, 256>>>(U, V, Wg, Wrad);
    prep_kernel<<<nc_blocks, 256>>>(node0, node1, node2, N);
    edge_kernel<<<444, 128>>>(rij, idx_i, idx_j, E);
    feat_kernel<<<nc_blocks, 256>>>(N);
    // y0 + gate (fused; y0 never leaves shared memory)
    y0gate_kernel<<<(N + 127) / 128, 256>>>((const float*)pF0, N);
    // y1 = F1 @ B1
    gemm_kernel<<<dim3((3 * N + 127) / 128, 1), 256>>>((const float*)pF1, (const float*)pB1,
                                                       (float*)pY1, 3 * N, 96, 32);
    // y2 = F2 @ B2
    gemm_kernel<<<dim3((9 * N + 127) / 128, 1), 256>>>((const float*)pF2, (const float*)pB2,
                                                       (float*)pY2, 9 * N, 128, 32);
    final_kernel<<<nc_blocks, 256>>>(node0, node1, node2, out, N);
}

// round 5
// speedup vs baseline: 1.1460x; 1.0002x over previous
#include <cuda_runtime.h>
#include <math.h>

#define NMAX 20000
#define EMAX 320000

// ---------------- scratch (device globals; no runtime allocation) ----------
__device__ float g_packed[NMAX * 32 * 16];   // per (n,c): [g0, g1[3], g2[9], pad3]
__device__ float g_acc[NMAX * 32 * 16];      // accumulated messages, same layout
__device__ float g_F0[NMAX * 128];           // features for y0 GEMM
__device__ float g_F1[NMAX * 3 * 96];        // features for y1 GEMM
__device__ float g_F2[NMAX * 9 * 128];       // features for y2 GEMM
__device__ float g_G [NMAX * 96];            // gate pre-activations
__device__ float g_Y1[NMAX * 3 * 32];
__device__ float g_Y2[NMAX * 9 * 32];
__device__ float g_B0[128 * 32];             // stacked [U0;V0;V3;V6]
__device__ float g_B1[96 * 32];              // stacked [U1;V1;V5]
__device__ float g_B2[128 * 32];             // stacked [U2;V2;V4;V7]
__device__ float g_Bg[32 * 96];              // [Wg0|Wg1|Wg2]
__device__ float2 g_W2[48 * 32];             // packed radial weights [b(8)][q(6)][c(32)]
                                             // pair q -> paths (2q, 2q+1), pre-scaled by exp(-4(delta*b)^2)

#define RBF_DELTA 0.6428571429f              // (5.0-0.5)/7

// ---------------- helpers ---------------------------------------------------
__device__ __forceinline__ void red_add_v4(float* addr, float x, float y, float z, float w) {
    asm volatile(
        "{\n\t"
        ".reg .u64 a;\n\t"
        "cvta.to.global.u64 a, %0;\n\t"
        "red.global.add.v4.f32 [a], {%1, %2, %3, %4};\n\t"
        "}"
        :: "l"(addr), "f"(x), "f"(y), "f"(z), "f"(w) : "memory");
}
__device__ __forceinline__ void red_add_f32(float* addr, float x) {
    asm volatile(
        "{\n\t"
        ".reg .u64 a;\n\t"
        "cvta.to.global.u64 a, %0;\n\t"
        "red.global.add.f32 [a], %1;\n\t"
        "}"
        :: "l"(addr), "f"(x) : "memory");
}
__device__ __forceinline__ void ffma2(unsigned long long& d, unsigned long long a,
                                      unsigned long long b) {
    asm("fma.rn.f32x2 %0, %1, %2, %0;" : "+l"(d) : "l"(a), "l"(b));
}
__device__ __forceinline__ unsigned long long pack2(float lo, float hi) {
    unsigned long long r;
    asm("mov.b64 %0, {%1, %2};" : "=l"(r) : "f"(lo), "f"(hi));
    return r;
}
__device__ __forceinline__ void unpack2(unsigned long long v, float& lo, float& hi) {
    asm("mov.b64 {%0, %1}, %2;" : "=f"(lo), "=f"(hi) : "l"(v));
}

// ---------------- kernel 0: pack stacked weight matrices -------------------
__global__ void pack_weights(const float* __restrict__ U, const float* __restrict__ V,
                             const float* __restrict__ Wg, const float* __restrict__ Wrad) {
    int t = blockIdx.x * blockDim.x + threadIdx.x;
    if (t < 1024) {
        int c = t >> 5, d = t & 31;
        int cd = c * 32 + d;
        g_B0[t]        = U[cd];
        g_B0[1024 + t] = V[cd];
        g_B0[2048 + t] = V[3072 + cd];
        g_B0[3072 + t] = V[6144 + cd];
        g_B1[t]        = U[1024 + cd];
        g_B1[1024 + t] = V[1024 + cd];
        g_B1[2048 + t] = V[5120 + cd];
        g_B2[t]        = U[2048 + cd];
        g_B2[1024 + t] = V[2048 + cd];
        g_B2[2048 + t] = V[4096 + cd];
        g_B2[3072 + t] = V[7168 + cd];
        g_Bg[c * 96 + d]      = Wg[cd];
        g_Bg[c * 96 + 32 + d] = Wg[1024 + cd];
        g_Bg[c * 96 + 64 + d] = Wg[2048 + cd];
    }
    // packed radial weights: 48 pair-slots x 32 channels
    if (t < 1536) {
        int k = t >> 5, c = t & 31;
        int b = k / 6, q = k % 6;
        float db = RBF_DELTA * (float)b;
        float scale = expf(-4.f * db * db);
        int p0 = 2 * q, p1 = 2 * q + 1;
        float lo = Wrad[(p0 * 8 + b) * 32 + c] * scale;
        float hi = (p1 < 11) ? Wrad[(p1 * 8 + b) * 32 + c] * scale : 0.f;
        g_W2[k * 32 + c] = make_float2(lo, hi);
    }
}

// ---------------- kernel 1: repack node features + zero accumulator --------
__global__ void prep_kernel(const float* __restrict__ node0, const float* __restrict__ node1,
                            const float* __restrict__ node2, int N) {
    int t = blockIdx.x * blockDim.x + threadIdx.x;
    if (t >= N * 32) return;
    const float* p1 = &node1[(long)t * 3];
    const float* p2 = &node2[(long)t * 9];
    float4 o0 = make_float4(node0[t], p1[0], p1[1], p1[2]);
    float4 o1 = make_float4(p2[0], p2[1], p2[2], p2[3]);
    float4 o2 = make_float4(p2[4], p2[5], p2[6], p2[7]);
    float4 o3 = make_float4(p2[8], 0.f, 0.f, 0.f);
    float4* dp = (float4*)&g_packed[(long)t * 16];
    dp[0] = o0; dp[1] = o1; dp[2] = o2; dp[3] = o3;
    float4 z = make_float4(0.f, 0.f, 0.f, 0.f);
    float4* da = (float4*)&g_acc[(long)t * 16];
    da[0] = z; da[1] = z; da[2] = z; da[3] = z;
}

// ---------------- kernel 2: edge messages + scatter -------------------------
// One warp per edge, lane = channel. Radial weights live in 96 registers/lane.
// rbf_b = base * rho^b with constants folded into g_W2; filter accumulated in
// packed f32x2 (48 FFMA2 instead of 88 LDS+FFMA).
__global__ void __launch_bounds__(128, 3)
edge_kernel(const float* __restrict__ rij,
            const int* __restrict__ idx_i, const int* __restrict__ idx_j, int E) {
    int lane = threadIdx.x & 31;
    int warp = threadIdx.x >> 5;
    unsigned long long Wreg[48];
    const unsigned long long* wsrc = (const unsigned long long*)g_W2;
    #pragma unroll
    for (int k = 0; k < 48; k++) Wreg[k] = wsrc[k * 32 + lane];

    int gw = blockIdx.x * 4 + warp;
    int stride = gridDim.x * 4;
    for (int e = gw; e < E; e += stride) {
        float rx = __ldg(&rij[e * 3 + 0]);
        float ry = __ldg(&rij[e * 3 + 1]);
        float rz = __ldg(&rij[e * 3 + 2]);
        int ii = __ldg(&idx_i[e]);
        int jj = __ldg(&idx_j[e]);
        float d2 = rx * rx + ry * ry + rz * rz + 1e-12f;
        float inv = rsqrtf(d2);
        float dist = d2 * inv;
        rx *= inv; ry *= inv; rz *= inv;
        float u = dist - 0.5f;
        float xx = fminf(dist * 0.2f, 1.0f);
        float fc = 0.5f * (__cosf(3.14159265358979f * xx) + 1.0f);
        float base = __expf(-4.f * u * u) * fc;
        float rho = __expf(fminf(8.f * RBF_DELTA * u, 80.f));

        unsigned long long wv[6];
        #pragma unroll
        for (int q = 0; q < 6; q++) wv[q] = 0ull;
        float t = base;
        #pragma unroll
        for (int b = 0; b < 8; b++) {
            unsigned long long tb = pack2(t, t);
            #pragma unroll
            for (int q = 0; q < 6; q++) ffma2(wv[q], tb, Wreg[b * 6 + q]);
            t *= rho;
        }
        float w[12];
        #pragma unroll
        for (int q = 0; q < 6; q++) unpack2(wv[q], w[2 * q], w[2 * q + 1]);

        // gather node_j features (13 used floats of the 16-float slot)
        const float* srcf = &g_packed[((long)jj * 32 + lane) * 16];
        float4 q0 = *(const float4*)(srcf + 0);
        float4 q1 = *(const float4*)(srcf + 4);
        float4 q2 = *(const float4*)(srcf + 8);
        float q3x = __ldg(srcf + 12);
        float g0 = q0.x, g1x = q0.y, g1y = q0.z, g1z = q0.w;
        float s1 = g1x * rx + g1y * ry + g1z * rz;
        float v2x = q1.x * rx + q1.y * ry + q1.z * rz;
        float v2y = q1.w * rx + q2.x * ry + q2.y * rz;
        float v2z = q2.z * rx + q2.w * ry + q3x * rz;
        float s2 = v2x * rx + v2y * ry + v2z * rz;
        // msg0
        float msg0 = g0 * w[0] + s1 * w[4] + s2 * w[9];
        // msg1[a] = (g0 w1 + s1 w6) r_a + w3 g1_a + w8 v2_a
        float cc = g0 * w[1] + s1 * w[6];
        float m1x = cc * rx + g1x * w[3] + w[8] * v2x;
        float m1y = cc * ry + g1y * w[3] + w[8] * v2y;
        float m1z = cc * rz + g1z * w[3] + w[8] * v2z;
        // msg2[ab] = w7 g2_ab + (g0 w2 r_a + w5 g1_a + w10 v2_a) r_b
        float g0w2 = g0 * w[2];
        float pax = g0w2 * rx + w[5] * g1x + w[10] * v2x;
        float pay = g0w2 * ry + w[5] * g1y + w[10] * v2y;
        float paz = g0w2 * rz + w[5] * g1z + w[10] * v2z;
        float* dst = &g_acc[((long)ii * 32 + lane) * 16];
        red_add_v4(dst + 0, msg0, m1x, m1y, m1z);
        red_add_v4(dst + 4,
                   w[7] * q1.x + pax * rx, w[7] * q1.y + pax * ry,
                   w[7] * q1.z + pax * rz, w[7] * q1.w + pay * rx);
        red_add_v4(dst + 8,
                   w[7] * q2.x + pay * ry, w[7] * q2.y + pay * rz,
                   w[7] * q2.z + paz * rx, w[7] * q2.w + paz * ry);
        red_add_f32(dst + 12, w[7] * q3x + paz * rz);
    }
}

// ---------------- kernel 3: build GEMM feature matrices --------------------
__global__ void feat_kernel(int N) {
    int t = blockIdx.x * blockDim.x + threadIdx.x;
    if (t >= N * 32) return;
    int n = t >> 5, c = t & 31;
    const float4* src = (const float4*)&g_acc[(long)t * 16];
    float4 q0 = src[0], q1 = src[1], q2 = src[2], q3 = src[3];
    const float s = 1.f / 16.f;   // NORM_FACTOR
    float a0 = q0.x * s;
    float a1[3] = {q0.y * s, q0.z * s, q0.w * s};
    float a2[9] = {q1.x * s, q1.y * s, q1.z * s, q1.w * s,
                   q2.x * s, q2.y * s, q2.z * s, q2.w * s, q3.x * s};
    float* f0 = &g_F0[(long)n * 128];
    f0[c]      = a0;
    f0[32 + c] = a0 * a0;
    f0[64 + c] = a1[0] * a1[0] + a1[1] * a1[1] + a1[2] * a1[2];
    float s22 = 0.f;
    #pragma unroll
    for (int i = 0; i < 9; i++) s22 += a2[i] * a2[i];
    f0[96 + c] = s22;
    #pragma unroll
    for (int a = 0; a < 3; a++) {
        float* f1 = &g_F1[((long)n * 3 + a) * 96];
        f1[c]      = a1[a];
        f1[32 + c] = a0 * a1[a];
        f1[64 + c] = a1[0] * a2[a] + a1[1] * a2[3 + a] + a1[2] * a2[6 + a];
    }
    #pragma unroll
    for (int a = 0; a < 3; a++) {
        #pragma unroll
        for (int b = 0; b < 3; b++) {
            int sidx = a * 3 + b;
            float* f2 = &g_F2[((long)n * 9 + sidx) * 128];
            f2[c]      = a2[sidx];
            f2[32 + c] = a0 * a2[sidx];
            f2[64 + c] = a1[a] * a1[b];
            f2[96 + c] = a2[a * 3 + 0] * a2[b] + a2[a * 3 + 1] * a2[3 + b]
                       + a2[a * 3 + 2] * a2[6 + b];
        }
    }
}

// ---------------- kernel 4: tiled fp32 GEMM  C[M,NC] = A[M,K] @ B[K,NC] ----
__global__ void gemm_kernel(const float* __restrict__ A, const float* __restrict__ B,
                            float* __restrict__ Cmat, int M, int K, int NC) {
    __shared__ float sA[128 * 33];
    __shared__ float sB[32 * 32];
    int tid = threadIdx.x;
    int m0 = blockIdx.x * 128;
    int cblk = blockIdx.y * 32;
    int dg = tid & 7, rg = tid >> 3;
    int c0 = dg * 4, r0 = rg * 4;
    float acc[4][4] = {};
    for (int kc = 0; kc < K; kc += 32) {
        for (int idx = tid; idx < 128 * 32; idx += 256) {
            int r = idx >> 5, kk = idx & 31;
            int m = m0 + r;
            sA[r * 33 + kk] = (m < M) ? A[(long)m * K + kc + kk] : 0.f;
        }
        for (int idx = tid; idx < 32 * 32; idx += 256) {
            int kk = idx >> 5, d = idx & 31;
            sB[kk * 32 + d] = B[(long)(kc + kk) * NC + cblk + d];
        }
        __syncthreads();
        #pragma unroll
        for (int kk = 0; kk < 32; kk++) {
            float4 b4 = *(const float4*)&sB[kk * 32 + c0];
            #pragma unroll
            for (int i = 0; i < 4; i++) {
                float a = sA[(r0 + i) * 33 + kk];
                acc[i][0] += a * b4.x;
                acc[i][1] += a * b4.y;
                acc[i][2] += a * b4.z;
                acc[i][3] += a * b4.w;
            }
        }
        __syncthreads();
    }
    #pragma unroll
    for (int i = 0; i < 4; i++) {
        int m = m0 + r0 + i;
        if (m < M) {
            float4 v = make_float4(acc[i][0], acc[i][1], acc[i][2], acc[i][3]);
            *(float4*)&Cmat[(long)m * NC + cblk + c0] = v;
        }
    }
}

// ---------------- kernel 4b: fused y0 GEMM + gate GEMM ---------------------
// stage 1: y0 = F0[128 rows x 128] @ B0[128 x 32]  (kept in smem only)
// stage 2: G  = y0 @ Bg[32 x 96]                    (written to g_G)
__global__ void y0gate_kernel(const float* __restrict__ F0, int N) {
    __shared__ float sA[128 * 33];
    __shared__ float sB[32 * 32];
    __shared__ float sY[128 * 33];
    int tid = threadIdx.x;
    int m0 = blockIdx.x * 128;
    int dg = tid & 7, rg = tid >> 3;
    int c0 = dg * 4, r0 = rg * 4;
    float acc[4][4] = {};
    for (int kc = 0; kc < 128; kc += 32) {
        for (int idx = tid; idx < 128 * 32; idx += 256) {
            int r = idx >> 5, kk = idx & 31;
            int m = m0 + r;
            sA[r * 33 + kk] = (m < N) ? F0[(long)m * 128 + kc + kk] : 0.f;
        }
        for (int idx = tid; idx < 32 * 32; idx += 256) {
            int kk = idx >> 5, d = idx & 31;
            sB[kk * 32 + d] = g_B0[(kc + kk) * 32 + d];
        }
        __syncthreads();
        #pragma unroll
        for (int kk = 0; kk < 32; kk++) {
            float4 b4 = *(const float4*)&sB[kk * 32 + c0];
            #pragma unroll
            for (int i = 0; i < 4; i++) {
                float a = sA[(r0 + i) * 33 + kk];
                acc[i][0] += a * b4.x;
                acc[i][1] += a * b4.y;
                acc[i][2] += a * b4.z;
                acc[i][3] += a * b4.w;
            }
        }
        __syncthreads();
    }
    // stash y0 tile in shared
    #pragma unroll
    for (int i = 0; i < 4; i++) {
        #pragma unroll
        for (int j = 0; j < 4; j++) sY[(r0 + i) * 33 + c0 + j] = acc[i][j];
    }
    __syncthreads();
    // stage 2: three 32-column segments of the gate matrix
    for (int seg = 0; seg < 3; seg++) {
        for (int idx = tid; idx < 32 * 32; idx += 256) {
            int kk = idx >> 5, d = idx & 31;
            sB[kk * 32 + d] = g_Bg[kk * 96 + seg * 32 + d];
        }
        __syncthreads();
        float acc2[4][4] = {};
        #pragma unroll
        for (int kk = 0; kk < 32; kk++) {
            float4 b4 = *(const float4*)&sB[kk * 32 + c0];
            #pragma unroll
            for (int i = 0; i < 4; i++) {
                float a = sY[(r0 + i) * 33 + kk];
                acc2[i][0] += a * b4.x;
                acc2[i][1] += a * b4.y;
                acc2[i][2] += a * b4.z;
                acc2[i][3] += a * b4.w;
            }
        }
        #pragma unroll
        for (int i = 0; i < 4; i++) {
            int m = m0 + r0 + i;
            if (m < N) {
                float4 v = make_float4(acc2[i][0], acc2[i][1], acc2[i][2], acc2[i][3]);
                *(float4*)&g_G[(long)m * 96 + seg * 32 + c0] = v;
            }
        }
        __syncthreads();
    }
}

// ---------------- kernel 5: gated nonlinearity + residual ------------------
__global__ void final_kernel(const float* __restrict__ node0, const float* __restrict__ node1,
                             const float* __restrict__ node2, float* __restrict__ out, int N) {
    int t = blockIdx.x * blockDim.x + threadIdx.x;
    if (t >= N * 32) return;
    int n = t >> 5, d = t & 31;
    float ga = g_G[(long)n * 96 + d];
    float gb = g_G[(long)n * 96 + 32 + d];
    float gc = g_G[(long)n * 96 + 64 + d];
    float s0 = ga / (1.f + __expf(-ga));
    float s1 = gb / (1.f + __expf(-gb));
    float s2 = gc / (1.f + __expf(-gc));
    out[t] = node0[t] + s0;
    long base1 = (long)N * 32;
    #pragma unroll
    for (int a = 0; a < 3; a++)
        out[base1 + (long)t * 3 + a] =
            node1[(long)t * 3 + a] + g_Y1[((long)n * 3 + a) * 32 + d] * s1;
    long base2 = (long)N * 128;
    #pragma unroll
    for (int sdx = 0; sdx < 9; sdx++)
        out[base2 + (long)t * 9 + sdx] =
            node2[(long)t * 9 + sdx] + g_Y2[((long)n * 9 + sdx) * 32 + d] * s2;
}

// ---------------- launch ----------------------------------------------------
extern "C" void kernel_launch(void* const* d_in, const int* in_sizes, int n_in,
                              void* d_out, int out_size) {
    const float* node0 = (const float*)d_in[0];
    const float* node1 = (const float*)d_in[1];
    const float* node2 = (const float*)d_in[2];
    const float* rij   = (const float*)d_in[3];
    const float* Wrad  = (const float*)d_in[4];
    const float* U     = (const float*)d_in[5];
    const float* V     = (const float*)d_in[6];
    const float* Wg    = (const float*)d_in[7];
    const int*   idx_i = (const int*)d_in[8];
    const int*   idx_j = (const int*)d_in[9];
    float* out = (float*)d_out;

    int N = in_sizes[0] / 32;
    int E = in_sizes[8];

    void *pF0, *pF1, *pF2, *pY1, *pY2, *pB1, *pB2;
    cudaGetSymbolAddress(&pF0, g_F0);
    cudaGetSymbolAddress(&pF1, g_F1);
    cudaGetSymbolAddress(&pF2, g_F2);
    cudaGetSymbolAddress(&pY1, g_Y1);
    cudaGetSymbolAddress(&pY2, g_Y2);
    cudaGetSymbolAddress(&pB1, g_B1);
    cudaGetSymbolAddress(&pB2, g_B2);

    int nc_blocks = (N * 32 + 255) / 256;

    pack_weights<<<8, 256>>>(U, V, Wg, Wrad);
    prep_kernel<<<nc_blocks, 256>>>(node0, node1, node2, N);
    edge_kernel<<<444, 128>>>(rij, idx_i, idx_j, E);
    feat_kernel<<<nc_blocks, 256>>>(N);
    // y0 + gate (fused; y0 never leaves shared memory)
    y0gate_kernel<<<(N + 127) / 128, 256>>>((const float*)pF0, N);
    // y1 = F1 @ B1
    gemm_kernel<<<dim3((3 * N + 127) / 128, 1), 256>>>((const float*)pF1, (const float*)pB1,
                                                       (float*)pY1, 3 * N, 96, 32);
    // y2 = F2 @ B2
    gemm_kernel<<<dim3((9 * N + 127) / 128, 1), 256>>>((const float*)pF2, (const float*)pB2,
                                                       (float*)pY2, 9 * N, 128, 32);
    final_kernel<<<nc_blocks, 256>>>(node0, node1, node2, out, N);
}

// round 6
// speedup vs baseline: 1.3829x; 1.2067x over previous
#include <cuda_runtime.h>
#include <math.h>

#define NMAX 20000
#define EMAX 320000

// ---------------- scratch (device globals; no runtime allocation) ----------
__device__ float g_packed[NMAX * 32 * 16];   // per (n,c): [g0, g1[3], g2[9], pad3]
__device__ float g_F0[NMAX * 128];           // features for y0 GEMM
__device__ float g_F1[NMAX * 3 * 96];        // features for y1 GEMM
__device__ float g_F2[NMAX * 9 * 128];       // features for y2 GEMM
__device__ float g_G [NMAX * 96];            // gate pre-activations
__device__ float g_Y1[NMAX * 3 * 32];
__device__ float g_Y2[NMAX * 9 * 32];
__device__ float g_B0[128 * 32];             // stacked [U0;V0;V3;V6]
__device__ float g_B1[96 * 32];              // stacked [U1;V1;V5]
__device__ float g_B2[128 * 32];             // stacked [U2;V2;V4;V7]
__device__ float g_Bg[32 * 96];              // [Wg0|Wg1|Wg2]
__device__ float2 g_W2[48 * 32];             // packed radial weights [b(8)][q(6)][c(32)]
// CSR-by-destination edge permutation
__device__ int g_cnt[NMAX];                  // per-node in-degree
__device__ int g_rowptr[NMAX];               // start offsets
__device__ int g_off[NMAX];                  // running offsets (scatter)
__device__ int g_perm[EMAX];                 // edge ids grouped by idx_i

#define RBF_DELTA 0.6428571429f              // (5.0-0.5)/7

// ---------------- helpers ---------------------------------------------------
__device__ __forceinline__ void ffma2(unsigned long long& d, unsigned long long a,
                                      unsigned long long b) {
    asm("fma.rn.f32x2 %0, %1, %2, %0;" : "+l"(d) : "l"(a), "l"(b));
}
__device__ __forceinline__ unsigned long long pack2(float lo, float hi) {
    unsigned long long r;
    asm("mov.b64 %0, {%1, %2};" : "=l"(r) : "f"(lo), "f"(hi));
    return r;
}
__device__ __forceinline__ void unpack2(unsigned long long v, float& lo, float& hi) {
    asm("mov.b64 {%0, %1}, %2;" : "=f"(lo), "=f"(hi) : "l"(v));
}

// ---------------- kernel 0: pack stacked weight matrices -------------------
__global__ void pack_weights(const float* __restrict__ U, const float* __restrict__ V,
                             const float* __restrict__ Wg, const float* __restrict__ Wrad) {
    int t = blockIdx.x * blockDim.x + threadIdx.x;
    if (t < 1024) {
        int c = t >> 5, d = t & 31;
        int cd = c * 32 + d;
        g_B0[t]        = U[cd];
        g_B0[1024 + t] = V[cd];
        g_B0[2048 + t] = V[3072 + cd];
        g_B0[3072 + t] = V[6144 + cd];
        g_B1[t]        = U[1024 + cd];
        g_B1[1024 + t] = V[1024 + cd];
        g_B1[2048 + t] = V[5120 + cd];
        g_B2[t]        = U[2048 + cd];
        g_B2[1024 + t] = V[2048 + cd];
        g_B2[2048 + t] = V[4096 + cd];
        g_B2[3072 + t] = V[7168 + cd];
        g_Bg[c * 96 + d]      = Wg[cd];
        g_Bg[c * 96 + 32 + d] = Wg[1024 + cd];
        g_Bg[c * 96 + 64 + d] = Wg[2048 + cd];
    }
    if (t < 1536) {
        int k = t >> 5, c = t & 31;
        int b = k / 6, q = k % 6;
        float db = RBF_DELTA * (float)b;
        float scale = expf(-4.f * db * db);
        int p0 = 2 * q, p1 = 2 * q + 1;
        float lo = Wrad[(p0 * 8 + b) * 32 + c] * scale;
        float hi = (p1 < 11) ? Wrad[(p1 * 8 + b) * 32 + c] * scale : 0.f;
        g_W2[k * 32 + c] = make_float2(lo, hi);
    }
}

// ---------------- kernel 1: repack node features + zero counters -----------
__global__ void prep_kernel(const float* __restrict__ node0, const float* __restrict__ node1,
                            const float* __restrict__ node2, int N) {
    int t = blockIdx.x * blockDim.x + threadIdx.x;
    if (t < N) g_cnt[t] = 0;
    if (t >= N * 32) return;
    const float* p1 = &node1[(long)t * 3];
    const float* p2 = &node2[(long)t * 9];
    float4 o0 = make_float4(node0[t], p1[0], p1[1], p1[2]);
    float4 o1 = make_float4(p2[0], p2[1], p2[2], p2[3]);
    float4 o2 = make_float4(p2[4], p2[5], p2[6], p2[7]);
    float4 o3 = make_float4(p2[8], 0.f, 0.f, 0.f);
    float4* dp = (float4*)&g_packed[(long)t * 16];
    dp[0] = o0; dp[1] = o1; dp[2] = o2; dp[3] = o3;
}

// ---------------- CSR build: histogram -> scan -> scatter ------------------
__global__ void hist_kernel(const int* __restrict__ idx_i, int E) {
    int e = blockIdx.x * blockDim.x + threadIdx.x;
    if (e < E) atomicAdd(&g_cnt[idx_i[e]], 1);
}

#define SCAN_T 512
__global__ void scan_kernel(int N) {
    __shared__ int s[SCAN_T];
    int chunk = (N + SCAN_T - 1) / SCAN_T;
    int start = threadIdx.x * chunk;
    int sum = 0;
    for (int i = 0; i < chunk; i++) {
        int idx = start + i;
        if (idx < N) sum += g_cnt[idx];
    }
    s[threadIdx.x] = sum;
    __syncthreads();
    // Hillis-Steele inclusive scan
    for (int d = 1; d < SCAN_T; d <<= 1) {
        int v = (threadIdx.x >= d) ? s[threadIdx.x - d] : 0;
        __syncthreads();
        s[threadIdx.x] += v;
        __syncthreads();
    }
    int run = (threadIdx.x == 0) ? 0 : s[threadIdx.x - 1];
    for (int i = 0; i < chunk; i++) {
        int idx = start + i;
        if (idx < N) {
            g_rowptr[idx] = run;
            g_off[idx]    = run;
            run += g_cnt[idx];
        }
    }
}

__global__ void scatter_kernel(const int* __restrict__ idx_i, int E) {
    int e = blockIdx.x * blockDim.x + threadIdx.x;
    if (e >= E) return;
    int pos = atomicAdd(&g_off[idx_i[e]], 1);
    g_perm[pos] = e;
}

// ---------------- kernel 2: warp-per-node gather + message + features ------
// lane = channel. Radial weights in 96 registers/lane. No atomics: each warp
// owns node n, walks its CSR edge list, accumulates 13 message components in
// registers, then computes the GEMM feature rows (old feat_kernel) in place.
__global__ void __launch_bounds__(128, 3)
node_kernel(const float* __restrict__ rij, const int* __restrict__ idx_j, int N) {
    int lane = threadIdx.x & 31;
    int warp = threadIdx.x >> 5;
    unsigned long long Wreg[48];
    const unsigned long long* wsrc = (const unsigned long long*)g_W2;
    #pragma unroll
    for (int k = 0; k < 48; k++) Wreg[k] = wsrc[k * 32 + lane];

    int n = blockIdx.x * 4 + warp;
    if (n >= N) return;

    float A0 = 0.f, A1x = 0.f, A1y = 0.f, A1z = 0.f;
    float A2[9] = {0.f, 0.f, 0.f, 0.f, 0.f, 0.f, 0.f, 0.f, 0.f};

    int s = g_rowptr[n];
    int cnt = g_cnt[n];

    float rx = 0.f, ry = 0.f, rz = 0.f;
    int jj = 0;
    if (cnt > 0) {
        int e = __ldg(&g_perm[s]);
        rx = __ldg(&rij[e * 3 + 0]);
        ry = __ldg(&rij[e * 3 + 1]);
        rz = __ldg(&rij[e * 3 + 2]);
        jj = __ldg(&idx_j[e]);
    }

    for (int k = 0; k < cnt; k++) {
        // gather node_j features (this edge) — issue before the w-filter math
        const float* srcf = &g_packed[((long)jj * 32 + lane) * 16];
        float4 q0 = *(const float4*)(srcf + 0);
        float4 q1 = *(const float4*)(srcf + 4);
        float4 q2 = *(const float4*)(srcf + 8);
        float q3x = srcf[12];
        float crx = rx, cry = ry, crz = rz;
        // prefetch next edge meta
        if (k + 1 < cnt) {
            int en = __ldg(&g_perm[s + k + 1]);
            rx = __ldg(&rij[en * 3 + 0]);
            ry = __ldg(&rij[en * 3 + 1]);
            rz = __ldg(&rij[en * 3 + 2]);
            jj = __ldg(&idx_j[en]);
        }
        // radial basis + filter (overlaps the gather's L2 latency)
        float d2 = crx * crx + cry * cry + crz * crz + 1e-12f;
        float inv = rsqrtf(d2);
        float dist = d2 * inv;
        crx *= inv; cry *= inv; crz *= inv;
        float u = dist - 0.5f;
        float xv = fminf(dist * 0.2f, 1.0f);
        float fc = 0.5f * (__cosf(3.14159265358979f * xv) + 1.0f);
        float base = __expf(-4.f * u * u) * fc;
        float rho = __expf(fminf(8.f * RBF_DELTA * u, 80.f));

        unsigned long long wv[6];
        #pragma unroll
        for (int q = 0; q < 6; q++) wv[q] = 0ull;
        float t = base;
        #pragma unroll
        for (int b = 0; b < 8; b++) {
            unsigned long long tb = pack2(t, t);
            #pragma unroll
            for (int q = 0; q < 6; q++) ffma2(wv[q], tb, Wreg[b * 6 + q]);
            t *= rho;
        }
        float w[12];
        #pragma unroll
        for (int q = 0; q < 6; q++) unpack2(wv[q], w[2 * q], w[2 * q + 1]);

        float g0 = q0.x, g1x = q0.y, g1y = q0.z, g1z = q0.w;
        float s1 = g1x * crx + g1y * cry + g1z * crz;
        float v2x = q1.x * crx + q1.y * cry + q1.z * crz;
        float v2y = q1.w * crx + q2.x * cry + q2.y * crz;
        float v2z = q2.z * crx + q2.w * cry + q3x * crz;
        float s2 = v2x * crx + v2y * cry + v2z * crz;
        // msg0
        A0 += g0 * w[0] + s1 * w[4] + s2 * w[9];
        // msg1[a] = (g0 w1 + s1 w6) r_a + w3 g1_a + w8 v2_a
        float cc = g0 * w[1] + s1 * w[6];
        A1x += cc * crx + g1x * w[3] + w[8] * v2x;
        A1y += cc * cry + g1y * w[3] + w[8] * v2y;
        A1z += cc * crz + g1z * w[3] + w[8] * v2z;
        // msg2[ab] = w7 g2_ab + (g0 w2 r_a + w5 g1_a + w10 v2_a) r_b
        float g0w2 = g0 * w[2];
        float pax = g0w2 * crx + w[5] * g1x + w[10] * v2x;
        float pay = g0w2 * cry + w[5] * g1y + w[10] * v2y;
        float paz = g0w2 * crz + w[5] * g1z + w[10] * v2z;
        A2[0] += w[7] * q1.x + pax * crx;
        A2[1] += w[7] * q1.y + pax * cry;
        A2[2] += w[7] * q1.z + pax * crz;
        A2[3] += w[7] * q1.w + pay * crx;
        A2[4] += w[7] * q2.x + pay * cry;
        A2[5] += w[7] * q2.y + pay * crz;
        A2[6] += w[7] * q2.z + paz * crx;
        A2[7] += w[7] * q2.w + paz * cry;
        A2[8] += w[7] * q3x + paz * crz;
    }

    // ---- fused feature build (old feat_kernel), c = lane ----
    const float sN = 1.f / 16.f;   // NORM_FACTOR
    float a0 = A0 * sN;
    float a1[3] = {A1x * sN, A1y * sN, A1z * sN};
    float a2[9];
    #pragma unroll
    for (int i = 0; i < 9; i++) a2[i] = A2[i] * sN;

    int c = lane;
    float* f0 = &g_F0[(long)n * 128];
    f0[c]      = a0;
    f0[32 + c] = a0 * a0;
    f0[64 + c] = a1[0] * a1[0] + a1[1] * a1[1] + a1[2] * a1[2];
    float s22 = 0.f;
    #pragma unroll
    for (int i = 0; i < 9; i++) s22 += a2[i] * a2[i];
    f0[96 + c] = s22;
    #pragma unroll
    for (int a = 0; a < 3; a++) {
        float* f1 = &g_F1[((long)n * 3 + a) * 96];
        f1[c]      = a1[a];
        f1[32 + c] = a0 * a1[a];
        f1[64 + c] = a1[0] * a2[a] + a1[1] * a2[3 + a] + a1[2] * a2[6 + a];
    }
    #pragma unroll
    for (int a = 0; a < 3; a++) {
        #pragma unroll
        for (int b = 0; b < 3; b++) {
            int sidx = a * 3 + b;
            float* f2 = &g_F2[((long)n * 9 + sidx) * 128];
            f2[c]      = a2[sidx];
            f2[32 + c] = a0 * a2[sidx];
            f2[64 + c] = a1[a] * a1[b];
            f2[96 + c] = a2[a * 3 + 0] * a2[b] + a2[a * 3 + 1] * a2[3 + b]
                       + a2[a * 3 + 2] * a2[6 + b];
        }
    }
}

// ---------------- kernel 4: tiled fp32 GEMM  C[M,NC] = A[M,K] @ B[K,NC] ----
__global__ void gemm_kernel(const float* __restrict__ A, const float* __restrict__ B,
                            float* __restrict__ Cmat, int M, int K, int NC) {
    __shared__ float sA[128 * 33];
    __shared__ float sB[32 * 32];
    int tid = threadIdx.x;
    int m0 = blockIdx.x * 128;
    int cblk = blockIdx.y * 32;
    int dg = tid & 7, rg = tid >> 3;
    int c0 = dg * 4, r0 = rg * 4;
    float acc[4][4] = {};
    for (int kc = 0; kc < K; kc += 32) {
        for (int idx = tid; idx < 128 * 32; idx += 256) {
            int r = idx >> 5, kk = idx & 31;
            int m = m0 + r;
            sA[r * 33 + kk] = (m < M) ? A[(long)m * K + kc + kk] : 0.f;
        }
        for (int idx = tid; idx < 32 * 32; idx += 256) {
            int kk = idx >> 5, d = idx & 31;
            sB[kk * 32 + d] = B[(long)(kc + kk) * NC + cblk + d];
        }
        __syncthreads();
        #pragma unroll
        for (int kk = 0; kk < 32; kk++) {
            float4 b4 = *(const float4*)&sB[kk * 32 + c0];
            #pragma unroll
            for (int i = 0; i < 4; i++) {
                float a = sA[(r0 + i) * 33 + kk];
                acc[i][0] += a * b4.x;
                acc[i][1] += a * b4.y;
                acc[i][2] += a * b4.z;
                acc[i][3] += a * b4.w;
            }
        }
        __syncthreads();
    }
    #pragma unroll
    for (int i = 0; i < 4; i++) {
        int m = m0 + r0 + i;
        if (m < M) {
            float4 v = make_float4(acc[i][0], acc[i][1], acc[i][2], acc[i][3]);
            *(float4*)&Cmat[(long)m * NC + cblk + c0] = v;
        }
    }
}

// ---------------- kernel 4b: fused y0 GEMM + gate GEMM ---------------------
__global__ void y0gate_kernel(const float* __restrict__ F0, int N) {
    __shared__ float sA[128 * 33];
    __shared__ float sB[32 * 32];
    __shared__ float sY[128 * 33];
    int tid = threadIdx.x;
    int m0 = blockIdx.x * 128;
    int dg = tid & 7, rg = tid >> 3;
    int c0 = dg * 4, r0 = rg * 4;
    float acc[4][4] = {};
    for (int kc = 0; kc < 128; kc += 32) {
        for (int idx = tid; idx < 128 * 32; idx += 256) {
            int r = idx >> 5, kk = idx & 31;
            int m = m0 + r;
            sA[r * 33 + kk] = (m < N) ? F0[(long)m * 128 + kc + kk] : 0.f;
        }
        for (int idx = tid; idx < 32 * 32; idx += 256) {
            int kk = idx >> 5, d = idx & 31;
            sB[kk * 32 + d] = g_B0[(kc + kk) * 32 + d];
        }
        __syncthreads();
        #pragma unroll
        for (int kk = 0; kk < 32; kk++) {
            float4 b4 = *(const float4*)&sB[kk * 32 + c0];
            #pragma unroll
            for (int i = 0; i < 4; i++) {
                float a = sA[(r0 + i) * 33 + kk];
                acc[i][0] += a * b4.x;
                acc[i][1] += a * b4.y;
                acc[i][2] += a * b4.z;
                acc[i][3] += a * b4.w;
            }
        }
        __syncthreads();
    }
    #pragma unroll
    for (int i = 0; i < 4; i++) {
        #pragma unroll
        for (int j = 0; j < 4; j++) sY[(r0 + i) * 33 + c0 + j] = acc[i][j];
    }
    __syncthreads();
    for (int seg = 0; seg < 3; seg++) {
        for (int idx = tid; idx < 32 * 32; idx += 256) {
            int kk = idx >> 5, d = idx & 31;
            sB[kk * 32 + d] = g_Bg[kk * 96 + seg * 32 + d];
        }
        __syncthreads();
        float acc2[4][4] = {};
        #pragma unroll
        for (int kk = 0; kk < 32; kk++) {
            float4 b4 = *(const float4*)&sB[kk * 32 + c0];
            #pragma unroll
            for (int i = 0; i < 4; i++) {
                float a = sY[(r0 + i) * 33 + kk];
                acc2[i][0] += a * b4.x;
                acc2[i][1] += a * b4.y;
                acc2[i][2] += a * b4.z;
                acc2[i][3] += a * b4.w;
            }
        }
        #pragma unroll
        for (int i = 0; i < 4; i++) {
            int m = m0 + r0 + i;
            if (m < N) {
                float4 v = make_float4(acc2[i][0], acc2[i][1], acc2[i][2], acc2[i][3]);
                *(float4*)&g_G[(long)m * 96 + seg * 32 + c0] = v;
            }
        }
        __syncthreads();
    }
}

// ---------------- kernel 5: gated nonlinearity + residual ------------------
__global__ void final_kernel(const float* __restrict__ node0, const float* __restrict__ node1,
                             const float* __restrict__ node2, float* __restrict__ out, int N) {
    int t = blockIdx.x * blockDim.x + threadIdx.x;
    if (t >= N * 32) return;
    int n = t >> 5, d = t & 31;
    float ga = g_G[(long)n * 96 + d];
    float gb = g_G[(long)n * 96 + 32 + d];
    float gc = g_G[(long)n * 96 + 64 + d];
    float s0 = ga / (1.f + __expf(-ga));
    float s1 = gb / (1.f + __expf(-gb));
    float s2 = gc / (1.f + __expf(-gc));
    out[t] = node0[t] + s0;
    long base1 = (long)N * 32;
    #pragma unroll
    for (int a = 0; a < 3; a++)
        out[base1 + (long)t * 3 + a] =
            node1[(long)t * 3 + a] + g_Y1[((long)n * 3 + a) * 32 + d] * s1;
    long base2 = (long)N * 128;
    #pragma unroll
    for (int sdx = 0; sdx < 9; sdx++)
        out[base2 + (long)t * 9 + sdx] =
            node2[(long)t * 9 + sdx] + g_Y2[((long)n * 9 + sdx) * 32 + d] * s2;
}

// ---------------- launch ----------------------------------------------------
extern "C" void kernel_launch(void* const* d_in, const int* in_sizes, int n_in,
                              void* d_out, int out_size) {
    const float* node0 = (const float*)d_in[0];
    const float* node1 = (const float*)d_in[1];
    const float* node2 = (const float*)d_in[2];
    const float* rij   = (const float*)d_in[3];
    const float* Wrad  = (const float*)d_in[4];
    const float* U     = (const float*)d_in[5];
    const float* V     = (const float*)d_in[6];
    const float* Wg    = (const float*)d_in[7];
    const int*   idx_i = (const int*)d_in[8];
    const int*   idx_j = (const int*)d_in[9];
    float* out = (float*)d_out;

    int N = in_sizes[0] / 32;
    int E = in_sizes[8];

    void *pF0, *pF1, *pF2, *pY1, *pY2, *pB1, *pB2;
    cudaGetSymbolAddress(&pF0, g_F0);
    cudaGetSymbolAddress(&pF1, g_F1);
    cudaGetSymbolAddress(&pF2, g_F2);
    cudaGetSymbolAddress(&pY1, g_Y1);
    cudaGetSymbolAddress(&pY2, g_Y2);
    cudaGetSymbolAddress(&pB1, g_B1);
    cudaGetSymbolAddress(&pB2, g_B2);

    int nc_blocks = (N * 32 + 255) / 256;
    int e_blocks  = (E + 255) / 256;

    pack_weights<<<8, 256>>>(U, V, Wg, Wrad);
    prep_kernel<<<nc_blocks, 256>>>(node0, node1, node2, N);
    // CSR-by-destination build
    hist_kernel<<<e_blocks, 256>>>(idx_i, E);
    scan_kernel<<<1, SCAN_T>>>(N);
    scatter_kernel<<<e_blocks, 256>>>(idx_i, E);
    // fused gather + message + feature build (no atomics)
    node_kernel<<<(N + 3) / 4, 128>>>(rij, idx_j, N);
    // y0 + gate (fused; y0 never leaves shared memory)
    y0gate_kernel<<<(N + 127) / 128, 256>>>((const float*)pF0, N);
    // y1 = F1 @ B1
    gemm_kernel<<<dim3((3 * N + 127) / 128, 1), 256>>>((const float*)pF1, (const float*)pB1,
                                                       (float*)pY1, 3 * N, 96, 32);
    // y2 = F2 @ B2
    gemm_kernel<<<dim3((9 * N + 127) / 128, 1), 256>>>((const float*)pF2, (const float*)pB2,
                                                       (float*)pY2, 9 * N, 128, 32);
    final_kernel<<<nc_blocks, 256>>>(node0, node1, node2, out, N);
}